// round 12
// baseline (speedup 1.0000x reference)
#include <cuda_runtime.h>
#include <cuda_bf16.h>
#include <cstdint>

#define H 128
#define E 1048576
#define NV 262144
#define T 4096
#define NET 8
#define FD 1056   // 8*H + 32
#define HD 256    // 2*H
#define KS 132    // FD / 8 k-steps
#define ECAP 256
#define NCAP 256

// ---------------- scratch ---------------------------------------------------
__device__ int g_ecnt[T];
__device__ int g_ncnt[T];
__device__ int g_icnt[T];
__device__ int g_hcnt[T];
__device__ float4   g_emeta[(size_t)T * ECAP];
__device__ unsigned g_nlist[(size_t)T * NCAP];
__device__ float g_Af[(size_t)(T / 16) * KS * 128];
__device__ float g_Bf[(size_t)KS * 32 * 64];
__device__ float g_hidden[(size_t)T * HD];
__device__ float g_norm3[3];

typedef unsigned long long u64;

__device__ __forceinline__ float gelu_exact(float x) {
    return 0.5f * x * (1.0f + erff(x * 0.7071067811865476f));
}
__device__ __forceinline__ u64 pack2(float lo, float hi) {
    u64 r; asm("mov.b64 %0, {%1, %2};" : "=l"(r) : "f"(lo), "f"(hi)); return r;
}
__device__ __forceinline__ void fma2(u64& acc, u64 a, u64 b) {
    asm("fma.rn.f32x2 %0, %1, %2, %0;" : "+l"(acc) : "l"(a), "l"(b));
}
__device__ __forceinline__ void unpack2(u64 v, float& lo, float& hi) {
    asm("mov.b64 {%0, %1}, %2;" : "=f"(lo), "=f"(hi) : "l"(v));
}
__device__ __forceinline__ float to_tf32(float x) {
    uint32_t u; asm("cvt.rna.tf32.f32 %0, %1;" : "=r"(u) : "f"(x));
    return __uint_as_float(u);
}
__device__ __forceinline__ void mma8(float* c, const float4& a, const float2& b) {
    asm("mma.sync.aligned.m16n8k8.row.col.f32.tf32.tf32.f32 "
        "{%0,%1,%2,%3}, {%4,%5,%6,%7}, {%8,%9}, {%0,%1,%2,%3};"
        : "+f"(c[0]), "+f"(c[1]), "+f"(c[2]), "+f"(c[3])
        : "r"(__float_as_uint(a.x)), "r"(__float_as_uint(a.y)),
          "r"(__float_as_uint(a.z)), "r"(__float_as_uint(a.w)),
          "r"(__float_as_uint(b.x)), "r"(__float_as_uint(b.y)));
}
__device__ __forceinline__ void storeA(int m, int k, float v) {
    int kstep = k >> 3, kc = k & 7, mr = m & 15;
    int th = ((mr & 7) << 2) | (kc & 3);
    int reg = (mr >> 3) | ((kc >> 2) << 1);
    g_Af[((size_t)(m >> 4) * KS + kstep) * 128 + th * 4 + reg] = to_tf32(v);
}

// ---------------- init ------------------------------------------------------
__global__ void k_init() {
    int i = blockIdx.x * blockDim.x + threadIdx.x;
    if (i < T) { g_ecnt[i] = 0; g_ncnt[i] = 0; g_icnt[i] = 0; g_hcnt[i] = 0; }
    if (i < 3) g_norm3[i] = 0.0f;
}

// ---------------- W2 -> tf32 B-fragments ------------------------------------
__global__ void k_cvtB(const float* __restrict__ W2) {
    int i = blockIdx.x * blockDim.x + threadIdx.x;
    int k = i >> 8, n = i & 255;
    float v = to_tf32(W2[i]);
    int kstep = k >> 3, kc = k & 7;
    int th = ((n & 7) << 2) | (kc & 3);
    int reg = kc >> 2;
    g_Bf[((size_t)kstep * 32 + (n >> 3)) * 64 + th * 2 + reg] = v;
}

// ---------------- scatter into fixed-capacity buckets -----------------------
#define EBLK (E / 4 / 256)
#define NBLK (NV / 4 / 256)
__global__ void k_scatter(const int* __restrict__ ed, const int* __restrict__ esg,
                          const int* __restrict__ tli, const int* __restrict__ rel,
                          const float* __restrict__ tm, const int* __restrict__ esrc,
                          const int* __restrict__ nsg, const int* __restrict__ hop) {
    int b = blockIdx.x;
    if (b < EBLK) {
        int i = b * 256 + threadIdx.x;
        int4 d4 = ((const int4*)ed)[i];
        int4 s4 = ((const int4*)esg)[i];
        int4 r4 = ((const int4*)rel)[i];
        float4 t4 = ((const float4*)tm)[i];
        int4 sr4 = ((const int4*)esrc)[i];
        int dd[4] = {d4.x, d4.y, d4.z, d4.w};
        int ss[4] = {s4.x, s4.y, s4.z, s4.w};
        int rr[4] = {r4.x, r4.y, r4.z, r4.w};
        float tt[4] = {t4.x, t4.y, t4.z, t4.w};
        int sc[4] = {sr4.x, sr4.y, sr4.z, sr4.w};
#pragma unroll
        for (int q = 0; q < 4; q++) {
            if (dd[q] == __ldg(&tli[ss[q]])) {
                int pos = atomicAdd(&g_ecnt[ss[q]], 1);
                bool inb = (rr[q] < NET);
                if (inb) atomicAdd(&g_icnt[ss[q]], 1);
                float t = tt[q];
                unsigned pk = (unsigned)(i * 4 + q) | (inb ? 0x80000000u : 0u);
                float4 mt;
                mt.x = __uint_as_float(pk);
                mt.y = __int_as_float(sc[q]);
                mt.z = expf(-t);
                mt.w = expf(-t * (1.0f / 24.0f));
                g_emeta[(size_t)ss[q] * ECAP + pos] = mt;
            }
        }
    } else {
        int i = (b - EBLK) * 256 + threadIdx.x;
        int4 n4 = ((const int4*)nsg)[i];
        int4 h4 = ((const int4*)hop)[i];
        int nn[4] = {n4.x, n4.y, n4.z, n4.w};
        int hh[4] = {h4.x, h4.y, h4.z, h4.w};
#pragma unroll
        for (int q = 0; q < 4; q++) {
            int pos = atomicAdd(&g_ncnt[nn[q]], 1);
            bool h1 = (hh[q] == 1);
            if (h1) atomicAdd(&g_hcnt[nn[q]], 1);
            g_nlist[(size_t)nn[q] * NCAP + pos] =
                (unsigned)(i * 4 + q) | (h1 ? 0x80000000u : 0u);
        }
    }
}

// ---------------- block reduce helpers (128 threads) ------------------------
__device__ __forceinline__ float blk_sum(float v, float* sb) {
#pragma unroll
    for (int o = 16; o > 0; o >>= 1) v += __shfl_xor_sync(0xffffffffu, v, o);
    __syncthreads();
    if ((threadIdx.x & 31) == 0) sb[threadIdx.x >> 5] = v;
    __syncthreads();
    return sb[0] + sb[1] + sb[2] + sb[3];
}
__device__ __forceinline__ float blk_ln(float x, float* sb) {
    float m = blk_sum(x, sb) * (1.0f / 128.0f);
    float d = x - m;
    float v = blk_sum(d * d, sb) * (1.0f / 128.0f);
    return d * rsqrtf(v + 1e-5f);
}

// ---------------- merged aggregation: grid 3T, interleaved b%3 ---------------
__global__ void __launch_bounds__(128, 10) k_agg(const float* __restrict__ edge_repr,
                                                 const float* __restrict__ node_repr,
                                                 const float* __restrict__ W1,
                                                 const float* __restrict__ b1) {
    __shared__ __align__(16) char sbuf[4096 + 8192 + 128];
    float4*   smeta4 = (float4*)sbuf;
    unsigned* smetau = (unsigned*)sbuf;
    float* cmb  = (float*)(sbuf + 4096);
    float* scmb = (float*)(sbuf + 4096 + 8192);
    float* sb   = scmb + 24;

    int b = blockIdx.x;
    int type = b % 3;
    int t = b / 3;
    int tid = threadIdx.x;
    int wid = tid >> 5, lane = tid & 31;
    int c4 = lane << 2;
    int h = tid;

    if (type == 0) {
        int ecount = g_ecnt[t];
        const float4* ebase = g_emeta + (size_t)t * ECAP;
        for (int i = tid; i < ecount; i += 128) smeta4[i] = ebase[i];
        __syncthreads();

        float4 v_is = {0,0,0,0}, v_os = {0,0,0,0}, v_il = {0,0,0,0}, v_ol = {0,0,0,0};
        float d_is = 0, d_os = 0, d_il = 0, d_ol = 0, tsum = 0;
#pragma unroll 8
        for (int i = wid; i < ecount; i += 4) {
            float4 mt = smeta4[i];
            unsigned pk = __float_as_uint(mt.x);
            int eidx = pk & 0x7fffffff;
            float sw = mt.z, lw = mt.w;
            float4 er = *(const float4*)(edge_repr + (size_t)eidx * H + c4);
            if (pk & 0x80000000u) {
                v_is.x += sw * er.x; v_is.y += sw * er.y; v_is.z += sw * er.z; v_is.w += sw * er.w;
                v_il.x += lw * er.x; v_il.y += lw * er.y; v_il.z += lw * er.z; v_il.w += lw * er.w;
                d_is += sw; d_il += lw;
            } else {
                v_os.x += sw * er.x; v_os.y += sw * er.y; v_os.z += sw * er.z; v_os.w += sw * er.w;
                v_ol.x += lw * er.x; v_ol.y += lw * er.y; v_ol.z += lw * er.z; v_ol.w += lw * er.w;
                d_os += sw; d_ol += lw;
            }
            tsum += -__logf(sw);
        }

        *(float4*)&cmb[(wid * 4 + 0) * 128 + c4] = v_is;
        *(float4*)&cmb[(wid * 4 + 1) * 128 + c4] = v_os;
        *(float4*)&cmb[(wid * 4 + 2) * 128 + c4] = v_il;
        *(float4*)&cmb[(wid * 4 + 3) * 128 + c4] = v_ol;
        if (lane == 0) {
            scmb[wid * 5 + 0] = d_is; scmb[wid * 5 + 1] = d_os;
            scmb[wid * 5 + 2] = d_il; scmb[wid * 5 + 3] = d_ol;
            scmb[wid * 5 + 4] = tsum;
        }
        __syncthreads();

        float a_is = cmb[0 * 128 + h] + cmb[4 * 128 + h] + cmb[8 * 128 + h] + cmb[12 * 128 + h];
        float a_os = cmb[1 * 128 + h] + cmb[5 * 128 + h] + cmb[9 * 128 + h] + cmb[13 * 128 + h];
        float a_il = cmb[2 * 128 + h] + cmb[6 * 128 + h] + cmb[10 * 128 + h] + cmb[14 * 128 + h];
        float a_ol = cmb[3 * 128 + h] + cmb[7 * 128 + h] + cmb[11 * 128 + h] + cmb[15 * 128 + h];
        d_is = scmb[0] + scmb[5] + scmb[10] + scmb[15];
        d_os = scmb[1] + scmb[6] + scmb[11] + scmb[16];
        d_il = scmb[2] + scmb[7] + scmb[12] + scmb[17];
        d_ol = scmb[3] + scmb[8] + scmb[13] + scmb[18];
        tsum = scmb[4] + scmb[9] + scmb[14] + scmb[19];

        float in_s  = a_is / fmaxf(d_is, 1e-6f);
        float out_s = a_os / fmaxf(d_os, 1e-6f);
        float in_l  = a_il / fmaxf(d_il, 1e-6f);
        float out_l = a_ol / fmaxf(d_ol, 1e-6f);

        float burst = blk_ln(in_s + out_s - in_l - out_l, sb);
        float dirg  = blk_ln(out_l - in_l, sb);
        float asym  = blk_ln(fabsf(dirg), sb);
        float rb    = blk_ln(in_l + out_l, sb);

        float ssd = blk_sum(dirg * dirg, sb);
        if (h == 0) atomicAdd(&g_norm3[2], sqrtf(ssd));

        storeA(t, 0 * H + h, burst);
        storeA(t, 1 * H + h, dirg);
        storeA(t, 4 * H + h, asym);
        storeA(t, 7 * H + h, rb);

        if (h < 32) {
            float cin = (float)g_icnt[t];
            float cnt = (float)ecount;
            float cout = cnt - cin;
            float c1 = (float)g_hcnt[t];
            float c2 = (float)g_ncnt[t] - c1;
            float smw = d_is + d_os;
            float lmw = d_il + d_ol;
            float s0 = log1pf(cin), s1 = log1pf(cout), s2 = log1pf(c1), s3 = log1pf(c2);
            float s4 = tsum / fmaxf(cnt, 1e-6f);
            float s5 = smw, s6 = lmw, s7 = smw - lmw;
            float acc = b1[h];
            acc += s0 * W1[0 * 32 + h] + s1 * W1[1 * 32 + h] + s2 * W1[2 * 32 + h] + s3 * W1[3 * 32 + h]
                 + s4 * W1[4 * 32 + h] + s5 * W1[5 * 32 + h] + s6 * W1[6 * 32 + h] + s7 * W1[7 * 32 + h];
            storeA(t, 8 * H + h, gelu_exact(acc));
        }
    } else if (type == 1) {
        int ecount = g_ecnt[t];
        const float4* ebase = g_emeta + (size_t)t * ECAP;
        for (int i = tid; i < ecount; i += 128) smeta4[i] = ebase[i];
        __syncthreads();

        float4 v_hs = {0,0,0,0}, v_hl = {0,0,0,0};
        float smw = 0, lmw = 0;
#pragma unroll 8
        for (int i = wid; i < ecount; i += 4) {
            float4 mt = smeta4[i];
            int src = __float_as_int(mt.y);
            float sw = mt.z, lw = mt.w;
            float4 sr = *(const float4*)(node_repr + (size_t)src * H + c4);
            v_hs.x += sw * sr.x; v_hs.y += sw * sr.y; v_hs.z += sw * sr.z; v_hs.w += sw * sr.w;
            v_hl.x += lw * sr.x; v_hl.y += lw * sr.y; v_hl.z += lw * sr.z; v_hl.w += lw * sr.w;
            smw += sw; lmw += lw;
        }
        *(float4*)&cmb[(wid * 2 + 0) * 128 + c4] = v_hs;
        *(float4*)&cmb[(wid * 2 + 1) * 128 + c4] = v_hl;
        if (lane == 0) { scmb[wid * 2 + 0] = smw; scmb[wid * 2 + 1] = lmw; }
        __syncthreads();

        float a_hs = cmb[0 * 128 + h] + cmb[2 * 128 + h] + cmb[4 * 128 + h] + cmb[6 * 128 + h];
        float a_hl = cmb[1 * 128 + h] + cmb[3 * 128 + h] + cmb[5 * 128 + h] + cmb[7 * 128 + h];
        smw = scmb[0] + scmb[2] + scmb[4] + scmb[6];
        lmw = scmb[1] + scmb[3] + scmb[5] + scmb[7];

        float h1es = a_hs / fmaxf(smw, 1e-6f);
        float h1el = a_hl / fmaxf(lmw, 1e-6f);
        float slg = blk_ln(h1es - h1el, sb);
        float sss = blk_sum(slg * slg, sb);
        if (h == 0) atomicAdd(&g_norm3[1], sqrtf(sss));
        storeA(t, 3 * H + h, slg);
    } else {
        int ncount = g_ncnt[t];
        const unsigned* nbase = g_nlist + (size_t)t * NCAP;
        for (int i = tid; i < ncount; i += 128) smetau[i] = nbase[i];
        __syncthreads();

        float4 v_h1 = {0,0,0,0}, v_h2 = {0,0,0,0};
#pragma unroll 8
        for (int i = wid; i < ncount; i += 4) {
            unsigned pk = smetau[i];
            float4 nr = *(const float4*)(node_repr + (size_t)(pk & 0x7fffffff) * H + c4);
            if (pk & 0x80000000u) {
                v_h1.x += nr.x; v_h1.y += nr.y; v_h1.z += nr.z; v_h1.w += nr.w;
            } else {
                v_h2.x += nr.x; v_h2.y += nr.y; v_h2.z += nr.z; v_h2.w += nr.w;
            }
        }
        *(float4*)&cmb[(wid * 2 + 0) * 128 + c4] = v_h1;
        *(float4*)&cmb[(wid * 2 + 1) * 128 + c4] = v_h2;
        __syncthreads();

        float a_h1 = cmb[0 * 128 + h] + cmb[2 * 128 + h] + cmb[4 * 128 + h] + cmb[6 * 128 + h];
        float a_h2 = cmb[1 * 128 + h] + cmb[3 * 128 + h] + cmb[5 * 128 + h] + cmb[7 * 128 + h];
        float c1 = (float)g_hcnt[t];
        float c2 = (float)ncount - c1;

        float h1m = a_h1 / fmaxf(c1, 1e-6f);
        float h2m = a_h2 / fmaxf(c2, 1e-6f);

        float hopg = blk_ln(h1m - h2m, sb);
        float h1n  = blk_ln(h1m, sb);
        float h2n  = blk_ln(h2m, sb);

        float ssh = blk_sum(hopg * hopg, sb);
        if (h == 0) atomicAdd(&g_norm3[0], sqrtf(ssh));

        storeA(t, 2 * H + h, hopg);
        storeA(t, 5 * H + h, h1n);
        storeA(t, 6 * H + h, h2n);
    }
}

// ---------------- GEMM1: tf32 mma.sync, 512 threads, warp tile 32x16 --------
// (round-10 proven config) 16 warps: wm=warp&3 (2 m16 tiles), wn=warp>>2 (2 n8).
// BM=128 BN=64, grid (32,4) = 128 blocks = one clean wave.
__global__ void __launch_bounds__(512) k_gemm1(const float* __restrict__ b2) {
    int tid = threadIdx.x, lane = tid & 31, warp = tid >> 5;
    int wm = warp & 3, wn = warp >> 2;
    int bm = blockIdx.x * 128, bn = blockIdx.y * 64;
    int mt0 = (bm >> 4) + wm * 2;
    int nt0 = (bn >> 3) + wn * 2;

    float c[2][2][4];
#pragma unroll
    for (int i = 0; i < 2; i++)
#pragma unroll
        for (int j = 0; j < 2; j++)
#pragma unroll
            for (int r = 0; r < 4; r++) c[i][j][r] = 0.0f;

    const float4* A0 = (const float4*)(g_Af + (size_t)mt0 * KS * 128) + lane;
    const float4* A1 = (const float4*)(g_Af + (size_t)(mt0 + 1) * KS * 128) + lane;
    const float2* B0 = (const float2*)g_Bf + (size_t)nt0 * 32 + lane;

#pragma unroll 4
    for (int ks = 0; ks < KS; ks++) {
        float4 a0 = A0[ks * 32];
        float4 a1 = A1[ks * 32];
        float2 bf0 = B0[(size_t)ks * 1024];
        float2 bf1 = B0[(size_t)ks * 1024 + 32];
        mma8(c[0][0], a0, bf0);
        mma8(c[1][0], a1, bf0);
        mma8(c[0][1], a0, bf1);
        mma8(c[1][1], a1, bf1);
    }

#pragma unroll
    for (int i = 0; i < 2; i++) {
        int r0 = bm + wm * 32 + i * 16 + (lane >> 2);
#pragma unroll
        for (int j = 0; j < 2; j++) {
            int cc = bn + wn * 16 + j * 8 + (lane & 3) * 2;
            float bx = b2[cc], by = b2[cc + 1];
            float2 lo, hi;
            lo.x = gelu_exact(c[i][j][0] + bx);
            lo.y = gelu_exact(c[i][j][1] + by);
            hi.x = gelu_exact(c[i][j][2] + bx);
            hi.y = gelu_exact(c[i][j][3] + by);
            *(float2*)(g_hidden + (size_t)r0 * HD + cc) = lo;
            *(float2*)(g_hidden + (size_t)(r0 + 8) * HD + cc) = hi;
        }
    }
}

// ---------------- GEMM2: [T,256] @ [256,128] + bias + 0.25*tanh + norms -----
__global__ void __launch_bounds__(256) k_gemm2(const float* __restrict__ W3,
                                               const float* __restrict__ b3,
                                               float* __restrict__ out) {
    __shared__ float hs[16 * 256];
    int tid = threadIdx.x;
    int t0 = blockIdx.x * 16;
    if (blockIdx.x == 0 && tid < 3)
        out[(size_t)T * H + tid] = g_norm3[tid] * (1.0f / (float)T);
    for (int i = tid; i < 16 * 256; i += 256)
        hs[i] = g_hidden[(size_t)t0 * 256 + i];
    __syncthreads();
    int n = tid & 127;
    int half = tid >> 7;
    const float* hp = hs + half * 8 * 256;
    u64 acc2[8];
#pragma unroll
    for (int r = 0; r < 8; r++) acc2[r] = 0ull;
    for (int k = 0; k < 256; k += 4) {
        float w0 = W3[(k + 0) * 128 + n];
        float w1 = W3[(k + 1) * 128 + n];
        float w2 = W3[(k + 2) * 128 + n];
        float w3v = W3[(k + 3) * 128 + n];
        u64 w01 = pack2(w0, w1);
        u64 w23 = pack2(w2, w3v);
#pragma unroll
        for (int r = 0; r < 8; r++) {
            ulonglong2 hv = *(const ulonglong2*)&hp[r * 256 + k];
            fma2(acc2[r], hv.x, w01);
            fma2(acc2[r], hv.y, w23);
        }
    }
    float bias = b3[n];
#pragma unroll
    for (int r = 0; r < 8; r++) {
        float lo, hi;
        unpack2(acc2[r], lo, hi);
        out[(size_t)(t0 + half * 8 + r) * 128 + n] = 0.25f * tanhf(lo + hi + bias);
    }
}

// ---------------- launcher --------------------------------------------------
extern "C" void kernel_launch(void* const* d_in, const int* in_sizes, int n_in,
                              void* d_out, int out_size) {
    const float* node_repr = (const float*)d_in[0];
    const float* edge_repr = (const float*)d_in[1];
    const int*   edge_src  = (const int*)d_in[2];
    const int*   edge_dst  = (const int*)d_in[3];
    const int*   rel_ids   = (const int*)d_in[4];
    const float* etime     = (const float*)d_in[5];
    const int*   tli       = (const int*)d_in[6];
    const int*   nsg       = (const int*)d_in[7];
    const int*   esg       = (const int*)d_in[8];
    const int*   hop       = (const int*)d_in[9];
    const float* W1 = (const float*)d_in[10];
    const float* b1 = (const float*)d_in[11];
    const float* W2 = (const float*)d_in[12];
    const float* b2 = (const float*)d_in[13];
    const float* W3 = (const float*)d_in[14];
    const float* b3 = (const float*)d_in[15];
    float* out = (float*)d_out;

    k_init<<<16, 256>>>();
    k_cvtB<<<FD * HD / 256, 256>>>(W2);
    k_scatter<<<EBLK + NBLK, 256>>>(edge_dst, esg, tli, rel_ids, etime, edge_src, nsg, hop);
    k_agg<<<3 * T, 128>>>(edge_repr, node_repr, W1, b1);
    k_gemm1<<<dim3(32, 4), 512>>>(b2);
    k_gemm2<<<T / 16, 256>>>(W3, b3, out);
}

// round 13
// speedup vs baseline: 1.0552x; 1.0552x over previous
#include <cuda_runtime.h>
#include <cuda_bf16.h>
#include <cstdint>

#define H 128
#define E 1048576
#define NV 262144
#define T 4096
#define NET 8
#define FD 1056   // 8*H + 32
#define HD 256    // 2*H
#define KS 132    // FD / 8 k-steps
#define ECAP 256
#define NCAP 256

// ---------------- scratch ---------------------------------------------------
__device__ int g_ecnt[T];   // low 16: edge count, high 16: inbound count
__device__ int g_ncnt[T];   // low 16: node count, high 16: hop1 count
__device__ float4   g_emeta[(size_t)T * ECAP];
__device__ unsigned g_nlist[(size_t)T * NCAP];
__device__ float g_Af[(size_t)(T / 16) * KS * 128];
__device__ float g_Bf[(size_t)KS * 32 * 64];
__device__ float g_hidden[(size_t)T * HD];
__device__ float g_norm3[3];

typedef unsigned long long u64;

__device__ __forceinline__ float gelu_exact(float x) {
    return 0.5f * x * (1.0f + erff(x * 0.7071067811865476f));
}
__device__ __forceinline__ u64 pack2(float lo, float hi) {
    u64 r; asm("mov.b64 %0, {%1, %2};" : "=l"(r) : "f"(lo), "f"(hi)); return r;
}
__device__ __forceinline__ void fma2(u64& acc, u64 a, u64 b) {
    asm("fma.rn.f32x2 %0, %1, %2, %0;" : "+l"(acc) : "l"(a), "l"(b));
}
__device__ __forceinline__ void unpack2(u64 v, float& lo, float& hi) {
    asm("mov.b64 {%0, %1}, %2;" : "=f"(lo), "=f"(hi) : "l"(v));
}
__device__ __forceinline__ float to_tf32(float x) {
    uint32_t u; asm("cvt.rna.tf32.f32 %0, %1;" : "=r"(u) : "f"(x));
    return __uint_as_float(u);
}
__device__ __forceinline__ void mma8(float* c, const float4& a, const float2& b) {
    asm("mma.sync.aligned.m16n8k8.row.col.f32.tf32.tf32.f32 "
        "{%0,%1,%2,%3}, {%4,%5,%6,%7}, {%8,%9}, {%0,%1,%2,%3};"
        : "+f"(c[0]), "+f"(c[1]), "+f"(c[2]), "+f"(c[3])
        : "r"(__float_as_uint(a.x)), "r"(__float_as_uint(a.y)),
          "r"(__float_as_uint(a.z)), "r"(__float_as_uint(a.w)),
          "r"(__float_as_uint(b.x)), "r"(__float_as_uint(b.y)));
}
__device__ __forceinline__ void storeA(int m, int k, float v) {
    int kstep = k >> 3, kc = k & 7, mr = m & 15;
    int th = ((mr & 7) << 2) | (kc & 3);
    int reg = (mr >> 3) | ((kc >> 2) << 1);
    g_Af[((size_t)(m >> 4) * KS + kstep) * 128 + th * 4 + reg] = to_tf32(v);
}

// ---------------- init + W2 -> tf32 B-fragments (merged) --------------------
__global__ void k_initcvt(const float* __restrict__ W2) {
    int i = blockIdx.x * blockDim.x + threadIdx.x;
    if (i < T) { g_ecnt[i] = 0; g_ncnt[i] = 0; }
    if (i < 3) g_norm3[i] = 0.0f;
    // B fragment convert: i covers FD*HD elements
    int k = i >> 8, n = i & 255;
    float v = to_tf32(W2[i]);
    int kstep = k >> 3, kc = k & 7;
    int th = ((n & 7) << 2) | (kc & 3);
    int reg = kc >> 2;
    g_Bf[((size_t)kstep * 32 + (n >> 3)) * 64 + th * 2 + reg] = v;
}

// ---------------- scatter into fixed-capacity buckets (packed atomics) ------
#define EBLK (E / 4 / 256)
#define NBLK (NV / 4 / 256)
__global__ void k_scatter(const int* __restrict__ ed, const int* __restrict__ esg,
                          const int* __restrict__ tli, const int* __restrict__ rel,
                          const float* __restrict__ tm, const int* __restrict__ esrc,
                          const int* __restrict__ nsg, const int* __restrict__ hop) {
    int b = blockIdx.x;
    if (b < EBLK) {
        int i = b * 256 + threadIdx.x;
        int4 d4 = ((const int4*)ed)[i];
        int4 s4 = ((const int4*)esg)[i];
        int4 r4 = ((const int4*)rel)[i];
        float4 t4 = ((const float4*)tm)[i];
        int4 sr4 = ((const int4*)esrc)[i];
        int dd[4] = {d4.x, d4.y, d4.z, d4.w};
        int ss[4] = {s4.x, s4.y, s4.z, s4.w};
        int rr[4] = {r4.x, r4.y, r4.z, r4.w};
        float tt[4] = {t4.x, t4.y, t4.z, t4.w};
        int sc[4] = {sr4.x, sr4.y, sr4.z, sr4.w};
#pragma unroll
        for (int q = 0; q < 4; q++) {
            if (dd[q] == __ldg(&tli[ss[q]])) {
                bool inb = (rr[q] < NET);
                int old = atomicAdd(&g_ecnt[ss[q]], inb ? 0x10001 : 1);
                int pos = old & 0xFFFF;
                float t = tt[q];
                unsigned pk = (unsigned)(i * 4 + q) | (inb ? 0x80000000u : 0u);
                float4 mt;
                mt.x = __uint_as_float(pk);
                mt.y = __int_as_float(sc[q]);
                mt.z = expf(-t);
                mt.w = expf(-t * (1.0f / 24.0f));
                g_emeta[(size_t)ss[q] * ECAP + pos] = mt;
            }
        }
    } else {
        int i = (b - EBLK) * 256 + threadIdx.x;
        int4 n4 = ((const int4*)nsg)[i];
        int4 h4 = ((const int4*)hop)[i];
        int nn[4] = {n4.x, n4.y, n4.z, n4.w};
        int hh[4] = {h4.x, h4.y, h4.z, h4.w};
#pragma unroll
        for (int q = 0; q < 4; q++) {
            bool h1 = (hh[q] == 1);
            int old = atomicAdd(&g_ncnt[nn[q]], h1 ? 0x10001 : 1);
            int pos = old & 0xFFFF;
            g_nlist[(size_t)nn[q] * NCAP + pos] =
                (unsigned)(i * 4 + q) | (h1 ? 0x80000000u : 0u);
        }
    }
}

// ---------------- block reduce helpers (128 threads) ------------------------
__device__ __forceinline__ float blk_sum(float v, float* sb) {
#pragma unroll
    for (int o = 16; o > 0; o >>= 1) v += __shfl_xor_sync(0xffffffffu, v, o);
    __syncthreads();
    if ((threadIdx.x & 31) == 0) sb[threadIdx.x >> 5] = v;
    __syncthreads();
    return sb[0] + sb[1] + sb[2] + sb[3];
}
__device__ __forceinline__ float blk_ln(float x, float* sb) {
    float m = blk_sum(x, sb) * (1.0f / 128.0f);
    float d = x - m;
    float v = blk_sum(d * d, sb) * (1.0f / 128.0f);
    return d * rsqrtf(v + 1e-5f);
}

// ---------------- merged aggregation: grid 3T, interleaved b%3 ---------------
__global__ void __launch_bounds__(128, 10) k_agg(const float* __restrict__ edge_repr,
                                                 const float* __restrict__ node_repr,
                                                 const float* __restrict__ W1,
                                                 const float* __restrict__ b1) {
    __shared__ __align__(16) char sbuf[4096 + 8192 + 128];
    float4*   smeta4 = (float4*)sbuf;
    unsigned* smetau = (unsigned*)sbuf;
    float* cmb  = (float*)(sbuf + 4096);
    float* scmb = (float*)(sbuf + 4096 + 8192);
    float* sb   = scmb + 24;

    int b = blockIdx.x;
    int type = b % 3;
    int t = b / 3;
    int tid = threadIdx.x;
    int wid = tid >> 5, lane = tid & 31;
    int c4 = lane << 2;
    int h = tid;

    if (type == 0) {
        int epk = g_ecnt[t];
        int ecount = epk & 0xFFFF;
        const float4* ebase = g_emeta + (size_t)t * ECAP;
        for (int i = tid; i < ecount; i += 128) smeta4[i] = ebase[i];
        __syncthreads();

        float4 v_is = {0,0,0,0}, v_os = {0,0,0,0}, v_il = {0,0,0,0}, v_ol = {0,0,0,0};
        float d_is = 0, d_os = 0, d_il = 0, d_ol = 0, tsum = 0;
#pragma unroll 4
        for (int i = wid; i < ecount; i += 4) {
            float4 mt = smeta4[i];
            unsigned pk = __float_as_uint(mt.x);
            int eidx = pk & 0x7fffffff;
            float sw = mt.z, lw = mt.w;
            float4 er = *(const float4*)(edge_repr + (size_t)eidx * H + c4);
            if (pk & 0x80000000u) {
                v_is.x += sw * er.x; v_is.y += sw * er.y; v_is.z += sw * er.z; v_is.w += sw * er.w;
                v_il.x += lw * er.x; v_il.y += lw * er.y; v_il.z += lw * er.z; v_il.w += lw * er.w;
                d_is += sw; d_il += lw;
            } else {
                v_os.x += sw * er.x; v_os.y += sw * er.y; v_os.z += sw * er.z; v_os.w += sw * er.w;
                v_ol.x += lw * er.x; v_ol.y += lw * er.y; v_ol.z += lw * er.z; v_ol.w += lw * er.w;
                d_os += sw; d_ol += lw;
            }
            tsum += -__logf(sw);
        }

        *(float4*)&cmb[(wid * 4 + 0) * 128 + c4] = v_is;
        *(float4*)&cmb[(wid * 4 + 1) * 128 + c4] = v_os;
        *(float4*)&cmb[(wid * 4 + 2) * 128 + c4] = v_il;
        *(float4*)&cmb[(wid * 4 + 3) * 128 + c4] = v_ol;
        if (lane == 0) {
            scmb[wid * 5 + 0] = d_is; scmb[wid * 5 + 1] = d_os;
            scmb[wid * 5 + 2] = d_il; scmb[wid * 5 + 3] = d_ol;
            scmb[wid * 5 + 4] = tsum;
        }
        __syncthreads();

        float a_is = cmb[0 * 128 + h] + cmb[4 * 128 + h] + cmb[8 * 128 + h] + cmb[12 * 128 + h];
        float a_os = cmb[1 * 128 + h] + cmb[5 * 128 + h] + cmb[9 * 128 + h] + cmb[13 * 128 + h];
        float a_il = cmb[2 * 128 + h] + cmb[6 * 128 + h] + cmb[10 * 128 + h] + cmb[14 * 128 + h];
        float a_ol = cmb[3 * 128 + h] + cmb[7 * 128 + h] + cmb[11 * 128 + h] + cmb[15 * 128 + h];
        d_is = scmb[0] + scmb[5] + scmb[10] + scmb[15];
        d_os = scmb[1] + scmb[6] + scmb[11] + scmb[16];
        d_il = scmb[2] + scmb[7] + scmb[12] + scmb[17];
        d_ol = scmb[3] + scmb[8] + scmb[13] + scmb[18];
        tsum = scmb[4] + scmb[9] + scmb[14] + scmb[19];

        float in_s  = a_is / fmaxf(d_is, 1e-6f);
        float out_s = a_os / fmaxf(d_os, 1e-6f);
        float in_l  = a_il / fmaxf(d_il, 1e-6f);
        float out_l = a_ol / fmaxf(d_ol, 1e-6f);

        float burst = blk_ln(in_s + out_s - in_l - out_l, sb);
        float dirg  = blk_ln(out_l - in_l, sb);
        float asym  = blk_ln(fabsf(dirg), sb);
        float rb    = blk_ln(in_l + out_l, sb);

        float ssd = blk_sum(dirg * dirg, sb);
        if (h == 0) atomicAdd(&g_norm3[2], sqrtf(ssd));

        storeA(t, 0 * H + h, burst);
        storeA(t, 1 * H + h, dirg);
        storeA(t, 4 * H + h, asym);
        storeA(t, 7 * H + h, rb);

        if (h < 32) {
            float cin = (float)(epk >> 16);
            float cnt = (float)ecount;
            float cout = cnt - cin;
            int npk = g_ncnt[t];
            float c1 = (float)(npk >> 16);
            float c2 = (float)(npk & 0xFFFF) - c1;
            float smw = d_is + d_os;
            float lmw = d_il + d_ol;
            float s0 = log1pf(cin), s1 = log1pf(cout), s2 = log1pf(c1), s3 = log1pf(c2);
            float s4 = tsum / fmaxf(cnt, 1e-6f);
            float s5 = smw, s6 = lmw, s7 = smw - lmw;
            float acc = b1[h];
            acc += s0 * W1[0 * 32 + h] + s1 * W1[1 * 32 + h] + s2 * W1[2 * 32 + h] + s3 * W1[3 * 32 + h]
                 + s4 * W1[4 * 32 + h] + s5 * W1[5 * 32 + h] + s6 * W1[6 * 32 + h] + s7 * W1[7 * 32 + h];
            storeA(t, 8 * H + h, gelu_exact(acc));
        }
    } else if (type == 1) {
        int ecount = g_ecnt[t] & 0xFFFF;
        const float4* ebase = g_emeta + (size_t)t * ECAP;
        for (int i = tid; i < ecount; i += 128) smeta4[i] = ebase[i];
        __syncthreads();

        float4 v_hs = {0,0,0,0}, v_hl = {0,0,0,0};
        float smw = 0, lmw = 0;
#pragma unroll 4
        for (int i = wid; i < ecount; i += 4) {
            float4 mt = smeta4[i];
            int src = __float_as_int(mt.y);
            float sw = mt.z, lw = mt.w;
            float4 sr = *(const float4*)(node_repr + (size_t)src * H + c4);
            v_hs.x += sw * sr.x; v_hs.y += sw * sr.y; v_hs.z += sw * sr.z; v_hs.w += sw * sr.w;
            v_hl.x += lw * sr.x; v_hl.y += lw * sr.y; v_hl.z += lw * sr.z; v_hl.w += lw * sr.w;
            smw += sw; lmw += lw;
        }
        *(float4*)&cmb[(wid * 2 + 0) * 128 + c4] = v_hs;
        *(float4*)&cmb[(wid * 2 + 1) * 128 + c4] = v_hl;
        if (lane == 0) { scmb[wid * 2 + 0] = smw; scmb[wid * 2 + 1] = lmw; }
        __syncthreads();

        float a_hs = cmb[0 * 128 + h] + cmb[2 * 128 + h] + cmb[4 * 128 + h] + cmb[6 * 128 + h];
        float a_hl = cmb[1 * 128 + h] + cmb[3 * 128 + h] + cmb[5 * 128 + h] + cmb[7 * 128 + h];
        smw = scmb[0] + scmb[2] + scmb[4] + scmb[6];
        lmw = scmb[1] + scmb[3] + scmb[5] + scmb[7];

        float h1es = a_hs / fmaxf(smw, 1e-6f);
        float h1el = a_hl / fmaxf(lmw, 1e-6f);
        float slg = blk_ln(h1es - h1el, sb);
        float sss = blk_sum(slg * slg, sb);
        if (h == 0) atomicAdd(&g_norm3[1], sqrtf(sss));
        storeA(t, 3 * H + h, slg);
    } else {
        int npk = g_ncnt[t];
        int ncount = npk & 0xFFFF;
        const unsigned* nbase = g_nlist + (size_t)t * NCAP;
        for (int i = tid; i < ncount; i += 128) smetau[i] = nbase[i];
        __syncthreads();

        float4 v_h1 = {0,0,0,0}, v_h2 = {0,0,0,0};
#pragma unroll 4
        for (int i = wid; i < ncount; i += 4) {
            unsigned pk = smetau[i];
            float4 nr = *(const float4*)(node_repr + (size_t)(pk & 0x7fffffff) * H + c4);
            if (pk & 0x80000000u) {
                v_h1.x += nr.x; v_h1.y += nr.y; v_h1.z += nr.z; v_h1.w += nr.w;
            } else {
                v_h2.x += nr.x; v_h2.y += nr.y; v_h2.z += nr.z; v_h2.w += nr.w;
            }
        }
        *(float4*)&cmb[(wid * 2 + 0) * 128 + c4] = v_h1;
        *(float4*)&cmb[(wid * 2 + 1) * 128 + c4] = v_h2;
        __syncthreads();

        float a_h1 = cmb[0 * 128 + h] + cmb[2 * 128 + h] + cmb[4 * 128 + h] + cmb[6 * 128 + h];
        float a_h2 = cmb[1 * 128 + h] + cmb[3 * 128 + h] + cmb[5 * 128 + h] + cmb[7 * 128 + h];
        float c1 = (float)(npk >> 16);
        float c2 = (float)ncount - c1;

        float h1m = a_h1 / fmaxf(c1, 1e-6f);
        float h2m = a_h2 / fmaxf(c2, 1e-6f);

        float hopg = blk_ln(h1m - h2m, sb);
        float h1n  = blk_ln(h1m, sb);
        float h2n  = blk_ln(h2m, sb);

        float ssh = blk_sum(hopg * hopg, sb);
        if (h == 0) atomicAdd(&g_norm3[0], sqrtf(ssh));

        storeA(t, 2 * H + h, hopg);
        storeA(t, 5 * H + h, h1n);
        storeA(t, 6 * H + h, h2n);
    }
}

// ---------------- GEMM1: tf32 mma.sync, BM=64 BN=64, 512 thr, grid (64,4) ---
// (round-11 proven config) 16 warps, warp tile 16x16, ~2 blocks/SM.
__global__ void __launch_bounds__(512) k_gemm1(const float* __restrict__ b2) {
    int tid = threadIdx.x, lane = tid & 31, warp = tid >> 5;
    int wm = warp & 3, wn = warp >> 2;
    int bm = blockIdx.x * 64, bn = blockIdx.y * 64;
    int mt = (bm >> 4) + wm;
    int nt0 = (bn >> 3) + wn * 2;

    float c[2][4];
#pragma unroll
    for (int j = 0; j < 2; j++)
#pragma unroll
        for (int r = 0; r < 4; r++) c[j][r] = 0.0f;

    const float4* A0 = (const float4*)(g_Af + (size_t)mt * KS * 128) + lane;
    const float2* B0 = (const float2*)g_Bf + (size_t)nt0 * 32 + lane;

#pragma unroll 4
    for (int ks = 0; ks < KS; ks++) {
        float4 a0 = A0[ks * 32];
        float2 bf0 = B0[(size_t)ks * 1024];
        float2 bf1 = B0[(size_t)ks * 1024 + 32];
        mma8(c[0], a0, bf0);
        mma8(c[1], a0, bf1);
    }

    int r0 = bm + wm * 16 + (lane >> 2);
#pragma unroll
    for (int j = 0; j < 2; j++) {
        int cc = bn + wn * 16 + j * 8 + (lane & 3) * 2;
        float bx = b2[cc], by = b2[cc + 1];
        float2 lo, hi;
        lo.x = gelu_exact(c[j][0] + bx);
        lo.y = gelu_exact(c[j][1] + by);
        hi.x = gelu_exact(c[j][2] + bx);
        hi.y = gelu_exact(c[j][3] + by);
        *(float2*)(g_hidden + (size_t)r0 * HD + cc) = lo;
        *(float2*)(g_hidden + (size_t)(r0 + 8) * HD + cc) = hi;
    }
}

// ---------------- GEMM2: [T,256] @ [256,128] + bias + 0.25*tanh + norms -----
__global__ void __launch_bounds__(256) k_gemm2(const float* __restrict__ W3,
                                               const float* __restrict__ b3,
                                               float* __restrict__ out) {
    __shared__ float hs[16 * 256];
    int tid = threadIdx.x;
    int t0 = blockIdx.x * 16;
    if (blockIdx.x == 0 && tid < 3)
        out[(size_t)T * H + tid] = g_norm3[tid] * (1.0f / (float)T);
    for (int i = tid; i < 16 * 256; i += 256)
        hs[i] = g_hidden[(size_t)t0 * 256 + i];
    __syncthreads();
    int n = tid & 127;
    int half = tid >> 7;
    const float* hp = hs + half * 8 * 256;
    u64 acc2[8];
#pragma unroll
    for (int r = 0; r < 8; r++) acc2[r] = 0ull;
    for (int k = 0; k < 256; k += 4) {
        float w0 = W3[(k + 0) * 128 + n];
        float w1 = W3[(k + 1) * 128 + n];
        float w2 = W3[(k + 2) * 128 + n];
        float w3v = W3[(k + 3) * 128 + n];
        u64 w01 = pack2(w0, w1);
        u64 w23 = pack2(w2, w3v);
#pragma unroll
        for (int r = 0; r < 8; r++) {
            ulonglong2 hv = *(const ulonglong2*)&hp[r * 256 + k];
            fma2(acc2[r], hv.x, w01);
            fma2(acc2[r], hv.y, w23);
        }
    }
    float bias = b3[n];
#pragma unroll
    for (int r = 0; r < 8; r++) {
        float lo, hi;
        unpack2(acc2[r], lo, hi);
        out[(size_t)(t0 + half * 8 + r) * 128 + n] = 0.25f * tanhf(lo + hi + bias);
    }
}

// ---------------- launcher --------------------------------------------------
extern "C" void kernel_launch(void* const* d_in, const int* in_sizes, int n_in,
                              void* d_out, int out_size) {
    const float* node_repr = (const float*)d_in[0];
    const float* edge_repr = (const float*)d_in[1];
    const int*   edge_src  = (const int*)d_in[2];
    const int*   edge_dst  = (const int*)d_in[3];
    const int*   rel_ids   = (const int*)d_in[4];
    const float* etime     = (const float*)d_in[5];
    const int*   tli       = (const int*)d_in[6];
    const int*   nsg       = (const int*)d_in[7];
    const int*   esg       = (const int*)d_in[8];
    const int*   hop       = (const int*)d_in[9];
    const float* W1 = (const float*)d_in[10];
    const float* b1 = (const float*)d_in[11];
    const float* W2 = (const float*)d_in[12];
    const float* b2 = (const float*)d_in[13];
    const float* W3 = (const float*)d_in[14];
    const float* b3 = (const float*)d_in[15];
    float* out = (float*)d_out;

    k_initcvt<<<FD * HD / 256, 256>>>(W2);
    k_scatter<<<EBLK + NBLK, 256>>>(edge_dst, esg, tli, rel_ids, etime, edge_src, nsg, hop);
    k_agg<<<3 * T, 128>>>(edge_repr, node_repr, W1, b1);
    k_gemm1<<<dim3(64, 4), 512>>>(b2);
    k_gemm2<<<T / 16, 256>>>(W3, b3, out);
}

// round 14
// speedup vs baseline: 1.1364x; 1.0770x over previous
#include <cuda_runtime.h>
#include <cuda_bf16.h>
#include <cstdint>

#define H 128
#define E 1048576
#define NV 262144
#define T 4096
#define NET 8
#define FD 1056   // 8*H + 32
#define HD 256    // 2*H
#define KS 132    // FD / 8 k-steps
#define ECAP 256
#define NCAP 256

// ---------------- scratch ---------------------------------------------------
__device__ int g_ecnt[T];   // low 16: edge count, high 16: inbound count
__device__ int g_ncnt[T];   // low 16: node count, high 16: hop1 count
__device__ float4   g_emeta[(size_t)T * ECAP];
__device__ unsigned g_nlist[(size_t)T * NCAP];
__device__ float g_Af[(size_t)(T / 16) * KS * 128];
__device__ float g_Bf[(size_t)KS * 32 * 64];
__device__ float g_hidden[(size_t)T * HD];
__device__ float g_norm3[3];

typedef unsigned long long u64;

__device__ __forceinline__ float gelu_exact(float x) {
    return 0.5f * x * (1.0f + erff(x * 0.7071067811865476f));
}
__device__ __forceinline__ u64 pack2(float lo, float hi) {
    u64 r; asm("mov.b64 %0, {%1, %2};" : "=l"(r) : "f"(lo), "f"(hi)); return r;
}
__device__ __forceinline__ void fma2(u64& acc, u64 a, u64 b) {
    asm("fma.rn.f32x2 %0, %1, %2, %0;" : "+l"(acc) : "l"(a), "l"(b));
}
__device__ __forceinline__ void unpack2(u64 v, float& lo, float& hi) {
    asm("mov.b64 {%0, %1}, %2;" : "=f"(lo), "=f"(hi) : "l"(v));
}
__device__ __forceinline__ float to_tf32(float x) {
    uint32_t u; asm("cvt.rna.tf32.f32 %0, %1;" : "=r"(u) : "f"(x));
    return __uint_as_float(u);
}
__device__ __forceinline__ void mma8(float* c, const float4& a, const float2& b) {
    asm("mma.sync.aligned.m16n8k8.row.col.f32.tf32.tf32.f32 "
        "{%0,%1,%2,%3}, {%4,%5,%6,%7}, {%8,%9}, {%0,%1,%2,%3};"
        : "+f"(c[0]), "+f"(c[1]), "+f"(c[2]), "+f"(c[3])
        : "r"(__float_as_uint(a.x)), "r"(__float_as_uint(a.y)),
          "r"(__float_as_uint(a.z)), "r"(__float_as_uint(a.w)),
          "r"(__float_as_uint(b.x)), "r"(__float_as_uint(b.y)));
}
__device__ __forceinline__ void storeA(int m, int k, float v) {
    int kstep = k >> 3, kc = k & 7, mr = m & 15;
    int th = ((mr & 7) << 2) | (kc & 3);
    int reg = (mr >> 3) | ((kc >> 2) << 1);
    g_Af[((size_t)(m >> 4) * KS + kstep) * 128 + th * 4 + reg] = to_tf32(v);
}

// ---------------- init + W2 -> tf32 B-fragments (merged) --------------------
__global__ void k_initcvt(const float* __restrict__ W2) {
    int i = blockIdx.x * blockDim.x + threadIdx.x;
    if (i < T) { g_ecnt[i] = 0; g_ncnt[i] = 0; }
    if (i < 3) g_norm3[i] = 0.0f;
    int k = i >> 8, n = i & 255;
    float v = to_tf32(W2[i]);
    int kstep = k >> 3, kc = k & 7;
    int th = ((n & 7) << 2) | (kc & 3);
    int reg = kc >> 2;
    g_Bf[((size_t)kstep * 32 + (n >> 3)) * 64 + th * 2 + reg] = v;
}

// ---------------- scatter into fixed-capacity buckets (packed atomics) ------
#define EBLK (E / 4 / 256)
#define NBLK (NV / 4 / 256)
__global__ void k_scatter(const int* __restrict__ ed, const int* __restrict__ esg,
                          const int* __restrict__ tli, const int* __restrict__ rel,
                          const float* __restrict__ tm, const int* __restrict__ esrc,
                          const int* __restrict__ nsg, const int* __restrict__ hop) {
    int b = blockIdx.x;
    if (b < EBLK) {
        int i = b * 256 + threadIdx.x;
        int4 d4 = ((const int4*)ed)[i];
        int4 s4 = ((const int4*)esg)[i];
        int4 r4 = ((const int4*)rel)[i];
        float4 t4 = ((const float4*)tm)[i];
        int4 sr4 = ((const int4*)esrc)[i];
        int dd[4] = {d4.x, d4.y, d4.z, d4.w};
        int ss[4] = {s4.x, s4.y, s4.z, s4.w};
        int rr[4] = {r4.x, r4.y, r4.z, r4.w};
        float tt[4] = {t4.x, t4.y, t4.z, t4.w};
        int sc[4] = {sr4.x, sr4.y, sr4.z, sr4.w};
#pragma unroll
        for (int q = 0; q < 4; q++) {
            if (dd[q] == __ldg(&tli[ss[q]])) {
                bool inb = (rr[q] < NET);
                int old = atomicAdd(&g_ecnt[ss[q]], inb ? 0x10001 : 1);
                int pos = old & 0xFFFF;
                float t = tt[q];
                unsigned pk = (unsigned)(i * 4 + q) | (inb ? 0x80000000u : 0u);
                float4 mt;
                mt.x = __uint_as_float(pk);
                mt.y = __int_as_float(sc[q]);
                mt.z = expf(-t);
                mt.w = expf(-t * (1.0f / 24.0f));
                g_emeta[(size_t)ss[q] * ECAP + pos] = mt;
            }
        }
    } else {
        int i = (b - EBLK) * 256 + threadIdx.x;
        int4 n4 = ((const int4*)nsg)[i];
        int4 h4 = ((const int4*)hop)[i];
        int nn[4] = {n4.x, n4.y, n4.z, n4.w};
        int hh[4] = {h4.x, h4.y, h4.z, h4.w};
#pragma unroll
        for (int q = 0; q < 4; q++) {
            bool h1 = (hh[q] == 1);
            int old = atomicAdd(&g_ncnt[nn[q]], h1 ? 0x10001 : 1);
            int pos = old & 0xFFFF;
            g_nlist[(size_t)nn[q] * NCAP + pos] =
                (unsigned)(i * 4 + q) | (h1 ? 0x80000000u : 0u);
        }
    }
}

// ---------------- block reduce helpers (128 threads) ------------------------
__device__ __forceinline__ float blk_sum(float v, float* sb) {
#pragma unroll
    for (int o = 16; o > 0; o >>= 1) v += __shfl_xor_sync(0xffffffffu, v, o);
    __syncthreads();
    if ((threadIdx.x & 31) == 0) sb[threadIdx.x >> 5] = v;
    __syncthreads();
    return sb[0] + sb[1] + sb[2] + sb[3];
}
__device__ __forceinline__ float blk_ln(float x, float* sb) {
    float m = blk_sum(x, sb) * (1.0f / 128.0f);
    float d = x - m;
    float v = blk_sum(d * d, sb) * (1.0f / 128.0f);
    return d * rsqrtf(v + 1e-5f);
}

// ---------------- merged aggregation: grid 3T, interleaved b%3 ---------------
__global__ void __launch_bounds__(128, 10) k_agg(const float* __restrict__ edge_repr,
                                                 const float* __restrict__ node_repr,
                                                 const float* __restrict__ W1,
                                                 const float* __restrict__ b1) {
    __shared__ __align__(16) char sbuf[4096 + 8192 + 128];
    float4*   smeta4 = (float4*)sbuf;
    unsigned* smetau = (unsigned*)sbuf;
    float* cmb  = (float*)(sbuf + 4096);
    float* scmb = (float*)(sbuf + 4096 + 8192);
    float* sb   = scmb + 24;

    int b = blockIdx.x;
    int type = b % 3;
    int t = b / 3;
    int tid = threadIdx.x;
    int wid = tid >> 5, lane = tid & 31;
    int c4 = lane << 2;
    int h = tid;

    if (type == 0) {
        int epk = g_ecnt[t];
        int ecount = epk & 0xFFFF;
        const float4* ebase = g_emeta + (size_t)t * ECAP;
        for (int i = tid; i < ecount; i += 128) smeta4[i] = ebase[i];
        __syncthreads();

        float4 v_is = {0,0,0,0}, v_os = {0,0,0,0}, v_il = {0,0,0,0}, v_ol = {0,0,0,0};
        float d_is = 0, d_os = 0, d_il = 0, d_ol = 0, tsum = 0;
#pragma unroll 4
        for (int i = wid; i < ecount; i += 4) {
            float4 mt = smeta4[i];
            unsigned pk = __float_as_uint(mt.x);
            int eidx = pk & 0x7fffffff;
            float sw = mt.z, lw = mt.w;
            float4 er = *(const float4*)(edge_repr + (size_t)eidx * H + c4);
            if (pk & 0x80000000u) {
                v_is.x += sw * er.x; v_is.y += sw * er.y; v_is.z += sw * er.z; v_is.w += sw * er.w;
                v_il.x += lw * er.x; v_il.y += lw * er.y; v_il.z += lw * er.z; v_il.w += lw * er.w;
                d_is += sw; d_il += lw;
            } else {
                v_os.x += sw * er.x; v_os.y += sw * er.y; v_os.z += sw * er.z; v_os.w += sw * er.w;
                v_ol.x += lw * er.x; v_ol.y += lw * er.y; v_ol.z += lw * er.z; v_ol.w += lw * er.w;
                d_os += sw; d_ol += lw;
            }
            tsum += -__logf(sw);
        }

        *(float4*)&cmb[(wid * 4 + 0) * 128 + c4] = v_is;
        *(float4*)&cmb[(wid * 4 + 1) * 128 + c4] = v_os;
        *(float4*)&cmb[(wid * 4 + 2) * 128 + c4] = v_il;
        *(float4*)&cmb[(wid * 4 + 3) * 128 + c4] = v_ol;
        if (lane == 0) {
            scmb[wid * 5 + 0] = d_is; scmb[wid * 5 + 1] = d_os;
            scmb[wid * 5 + 2] = d_il; scmb[wid * 5 + 3] = d_ol;
            scmb[wid * 5 + 4] = tsum;
        }
        __syncthreads();

        float a_is = cmb[0 * 128 + h] + cmb[4 * 128 + h] + cmb[8 * 128 + h] + cmb[12 * 128 + h];
        float a_os = cmb[1 * 128 + h] + cmb[5 * 128 + h] + cmb[9 * 128 + h] + cmb[13 * 128 + h];
        float a_il = cmb[2 * 128 + h] + cmb[6 * 128 + h] + cmb[10 * 128 + h] + cmb[14 * 128 + h];
        float a_ol = cmb[3 * 128 + h] + cmb[7 * 128 + h] + cmb[11 * 128 + h] + cmb[15 * 128 + h];
        d_is = scmb[0] + scmb[5] + scmb[10] + scmb[15];
        d_os = scmb[1] + scmb[6] + scmb[11] + scmb[16];
        d_il = scmb[2] + scmb[7] + scmb[12] + scmb[17];
        d_ol = scmb[3] + scmb[8] + scmb[13] + scmb[18];
        tsum = scmb[4] + scmb[9] + scmb[14] + scmb[19];

        float in_s  = a_is / fmaxf(d_is, 1e-6f);
        float out_s = a_os / fmaxf(d_os, 1e-6f);
        float in_l  = a_il / fmaxf(d_il, 1e-6f);
        float out_l = a_ol / fmaxf(d_ol, 1e-6f);

        float burst = blk_ln(in_s + out_s - in_l - out_l, sb);
        float dirg  = blk_ln(out_l - in_l, sb);
        float asym  = blk_ln(fabsf(dirg), sb);
        float rb    = blk_ln(in_l + out_l, sb);

        float ssd = blk_sum(dirg * dirg, sb);
        if (h == 0) atomicAdd(&g_norm3[2], sqrtf(ssd));

        storeA(t, 0 * H + h, burst);
        storeA(t, 1 * H + h, dirg);
        storeA(t, 4 * H + h, asym);
        storeA(t, 7 * H + h, rb);

        if (h < 32) {
            float cin = (float)(epk >> 16);
            float cnt = (float)ecount;
            float cout = cnt - cin;
            int npk = g_ncnt[t];
            float c1 = (float)(npk >> 16);
            float c2 = (float)(npk & 0xFFFF) - c1;
            float smw = d_is + d_os;
            float lmw = d_il + d_ol;
            float s0 = log1pf(cin), s1 = log1pf(cout), s2 = log1pf(c1), s3 = log1pf(c2);
            float s4 = tsum / fmaxf(cnt, 1e-6f);
            float s5 = smw, s6 = lmw, s7 = smw - lmw;
            float acc = b1[h];
            acc += s0 * W1[0 * 32 + h] + s1 * W1[1 * 32 + h] + s2 * W1[2 * 32 + h] + s3 * W1[3 * 32 + h]
                 + s4 * W1[4 * 32 + h] + s5 * W1[5 * 32 + h] + s6 * W1[6 * 32 + h] + s7 * W1[7 * 32 + h];
            storeA(t, 8 * H + h, gelu_exact(acc));
        }
    } else if (type == 1) {
        int ecount = g_ecnt[t] & 0xFFFF;
        const float4* ebase = g_emeta + (size_t)t * ECAP;
        for (int i = tid; i < ecount; i += 128) smeta4[i] = ebase[i];
        __syncthreads();

        float4 v_hs = {0,0,0,0}, v_hl = {0,0,0,0};
        float smw = 0, lmw = 0;
#pragma unroll 4
        for (int i = wid; i < ecount; i += 4) {
            float4 mt = smeta4[i];
            int src = __float_as_int(mt.y);
            float sw = mt.z, lw = mt.w;
            float4 sr = *(const float4*)(node_repr + (size_t)src * H + c4);
            v_hs.x += sw * sr.x; v_hs.y += sw * sr.y; v_hs.z += sw * sr.z; v_hs.w += sw * sr.w;
            v_hl.x += lw * sr.x; v_hl.y += lw * sr.y; v_hl.z += lw * sr.z; v_hl.w += lw * sr.w;
            smw += sw; lmw += lw;
        }
        *(float4*)&cmb[(wid * 2 + 0) * 128 + c4] = v_hs;
        *(float4*)&cmb[(wid * 2 + 1) * 128 + c4] = v_hl;
        if (lane == 0) { scmb[wid * 2 + 0] = smw; scmb[wid * 2 + 1] = lmw; }
        __syncthreads();

        float a_hs = cmb[0 * 128 + h] + cmb[2 * 128 + h] + cmb[4 * 128 + h] + cmb[6 * 128 + h];
        float a_hl = cmb[1 * 128 + h] + cmb[3 * 128 + h] + cmb[5 * 128 + h] + cmb[7 * 128 + h];
        smw = scmb[0] + scmb[2] + scmb[4] + scmb[6];
        lmw = scmb[1] + scmb[3] + scmb[5] + scmb[7];

        float h1es = a_hs / fmaxf(smw, 1e-6f);
        float h1el = a_hl / fmaxf(lmw, 1e-6f);
        float slg = blk_ln(h1es - h1el, sb);
        float sss = blk_sum(slg * slg, sb);
        if (h == 0) atomicAdd(&g_norm3[1], sqrtf(sss));
        storeA(t, 3 * H + h, slg);
    } else {
        int npk = g_ncnt[t];
        int ncount = npk & 0xFFFF;
        const unsigned* nbase = g_nlist + (size_t)t * NCAP;
        for (int i = tid; i < ncount; i += 128) smetau[i] = nbase[i];
        __syncthreads();

        float4 v_h1 = {0,0,0,0}, v_h2 = {0,0,0,0};
#pragma unroll 4
        for (int i = wid; i < ncount; i += 4) {
            unsigned pk = smetau[i];
            float4 nr = *(const float4*)(node_repr + (size_t)(pk & 0x7fffffff) * H + c4);
            if (pk & 0x80000000u) {
                v_h1.x += nr.x; v_h1.y += nr.y; v_h1.z += nr.z; v_h1.w += nr.w;
            } else {
                v_h2.x += nr.x; v_h2.y += nr.y; v_h2.z += nr.z; v_h2.w += nr.w;
            }
        }
        *(float4*)&cmb[(wid * 2 + 0) * 128 + c4] = v_h1;
        *(float4*)&cmb[(wid * 2 + 1) * 128 + c4] = v_h2;
        __syncthreads();

        float a_h1 = cmb[0 * 128 + h] + cmb[2 * 128 + h] + cmb[4 * 128 + h] + cmb[6 * 128 + h];
        float a_h2 = cmb[1 * 128 + h] + cmb[3 * 128 + h] + cmb[5 * 128 + h] + cmb[7 * 128 + h];
        float c1 = (float)(npk >> 16);
        float c2 = (float)ncount - c1;

        float h1m = a_h1 / fmaxf(c1, 1e-6f);
        float h2m = a_h2 / fmaxf(c2, 1e-6f);

        float hopg = blk_ln(h1m - h2m, sb);
        float h1n  = blk_ln(h1m, sb);
        float h2n  = blk_ln(h2m, sb);

        float ssh = blk_sum(hopg * hopg, sb);
        if (h == 0) atomicAdd(&g_norm3[0], sqrtf(ssh));

        storeA(t, 2 * H + h, hopg);
        storeA(t, 5 * H + h, h1n);
        storeA(t, 6 * H + h, h2n);
    }
}

// ---------------- GEMM1: tf32 mma.sync, BM=64 BN=64, 512 thr, grid (64,4) ---
// Batched loads: groups of 4 k-steps, 12 LDGs issued before any mma consumes.
__global__ void __launch_bounds__(512) k_gemm1(const float* __restrict__ b2) {
    int tid = threadIdx.x, lane = tid & 31, warp = tid >> 5;
    int wm = warp & 3, wn = warp >> 2;
    int bm = blockIdx.x * 64, bn = blockIdx.y * 64;
    int mt = (bm >> 4) + wm;
    int nt0 = (bn >> 3) + wn * 2;

    float c[2][4];
#pragma unroll
    for (int j = 0; j < 2; j++)
#pragma unroll
        for (int r = 0; r < 4; r++) c[j][r] = 0.0f;

    const float4* A0 = (const float4*)(g_Af + (size_t)mt * KS * 128) + lane;
    const float2* B0 = (const float2*)g_Bf + (size_t)nt0 * 32 + lane;

#pragma unroll 1
    for (int ks = 0; ks < KS; ks += 4) {
        float4 av[4]; float2 b0v[4], b1v[4];
#pragma unroll
        for (int u = 0; u < 4; u++) {
            av[u]  = A0[(ks + u) * 32];
            b0v[u] = B0[(size_t)(ks + u) * 1024];
            b1v[u] = B0[(size_t)(ks + u) * 1024 + 32];
        }
#pragma unroll
        for (int u = 0; u < 4; u++) {
            mma8(c[0], av[u], b0v[u]);
            mma8(c[1], av[u], b1v[u]);
        }
    }

    int r0 = bm + wm * 16 + (lane >> 2);
#pragma unroll
    for (int j = 0; j < 2; j++) {
        int cc = bn + wn * 16 + j * 8 + (lane & 3) * 2;
        float bx = b2[cc], by = b2[cc + 1];
        float2 lo, hi;
        lo.x = gelu_exact(c[j][0] + bx);
        lo.y = gelu_exact(c[j][1] + by);
        hi.x = gelu_exact(c[j][2] + bx);
        hi.y = gelu_exact(c[j][3] + by);
        *(float2*)(g_hidden + (size_t)r0 * HD + cc) = lo;
        *(float2*)(g_hidden + (size_t)(r0 + 8) * HD + cc) = hi;
    }
}

// ---------------- GEMM2: [T,256] @ [256,128] + bias + 0.25*tanh + norms -----
__global__ void __launch_bounds__(256) k_gemm2(const float* __restrict__ W3,
                                               const float* __restrict__ b3,
                                               float* __restrict__ out) {
    __shared__ float hs[16 * 256];
    int tid = threadIdx.x;
    int t0 = blockIdx.x * 16;
    if (blockIdx.x == 0 && tid < 3)
        out[(size_t)T * H + tid] = g_norm3[tid] * (1.0f / (float)T);
    for (int i = tid; i < 16 * 256; i += 256)
        hs[i] = g_hidden[(size_t)t0 * 256 + i];
    __syncthreads();
    int n = tid & 127;
    int half = tid >> 7;
    const float* hp = hs + half * 8 * 256;
    u64 acc2[8];
#pragma unroll
    for (int r = 0; r < 8; r++) acc2[r] = 0ull;
    for (int k = 0; k < 256; k += 4) {
        float w0 = W3[(k + 0) * 128 + n];
        float w1 = W3[(k + 1) * 128 + n];
        float w2 = W3[(k + 2) * 128 + n];
        float w3v = W3[(k + 3) * 128 + n];
        u64 w01 = pack2(w0, w1);
        u64 w23 = pack2(w2, w3v);
#pragma unroll
        for (int r = 0; r < 8; r++) {
            ulonglong2 hv = *(const ulonglong2*)&hp[r * 256 + k];
            fma2(acc2[r], hv.x, w01);
            fma2(acc2[r], hv.y, w23);
        }
    }
    float bias = b3[n];
#pragma unroll
    for (int r = 0; r < 8; r++) {
        float lo, hi;
        unpack2(acc2[r], lo, hi);
        out[(size_t)(t0 + half * 8 + r) * 128 + n] = 0.25f * tanhf(lo + hi + bias);
    }
}

// ---------------- launcher --------------------------------------------------
extern "C" void kernel_launch(void* const* d_in, const int* in_sizes, int n_in,
                              void* d_out, int out_size) {
    const float* node_repr = (const float*)d_in[0];
    const float* edge_repr = (const float*)d_in[1];
    const int*   edge_src  = (const int*)d_in[2];
    const int*   edge_dst  = (const int*)d_in[3];
    const int*   rel_ids   = (const int*)d_in[4];
    const float* etime     = (const float*)d_in[5];
    const int*   tli       = (const int*)d_in[6];
    const int*   nsg       = (const int*)d_in[7];
    const int*   esg       = (const int*)d_in[8];
    const int*   hop       = (const int*)d_in[9];
    const float* W1 = (const float*)d_in[10];
    const float* b1 = (const float*)d_in[11];
    const float* W2 = (const float*)d_in[12];
    const float* b2 = (const float*)d_in[13];
    const float* W3 = (const float*)d_in[14];
    const float* b3 = (const float*)d_in[15];
    float* out = (float*)d_out;

    k_initcvt<<<FD * HD / 256, 256>>>(W2);
    k_scatter<<<EBLK + NBLK, 256>>>(edge_dst, esg, tli, rel_ids, etime, edge_src, nsg, hop);
    k_agg<<<3 * T, 128>>>(edge_repr, node_repr, W1, b1);
    k_gemm1<<<dim3(64, 4), 512>>>(b2);
    k_gemm2<<<T / 16, 256>>>(W3, b3, out);
}

// round 15
// speedup vs baseline: 1.2440x; 1.0946x over previous
#include <cuda_runtime.h>
#include <cuda_bf16.h>
#include <cstdint>

#define H 128
#define E 1048576
#define NV 262144
#define T 4096
#define NET 8
#define FD 1056   // 8*H + 32
#define HD 256    // 2*H
#define KS 132    // FD / 8 k-steps
#define ECAP 256
#define NCAP 256

// ---------------- scratch ---------------------------------------------------
__device__ int g_ecnt[T];   // low 16: edge count, high 16: inbound count
__device__ int g_ncnt[T];   // low 16: node count, high 16: hop1 count
__device__ float4   g_emeta[(size_t)T * ECAP];
__device__ unsigned g_nlist[(size_t)T * NCAP];
__device__ float g_Af[(size_t)(T / 16) * KS * 128];
__device__ float g_Bf[(size_t)KS * 32 * 64];
__device__ float g_hidden[(size_t)T * HD];
__device__ float g_norm3[3];

typedef unsigned long long u64;

__device__ __forceinline__ float gelu_exact(float x) {
    return 0.5f * x * (1.0f + erff(x * 0.7071067811865476f));
}
__device__ __forceinline__ u64 pack2(float lo, float hi) {
    u64 r; asm("mov.b64 %0, {%1, %2};" : "=l"(r) : "f"(lo), "f"(hi)); return r;
}
__device__ __forceinline__ void fma2(u64& acc, u64 a, u64 b) {
    asm("fma.rn.f32x2 %0, %1, %2, %0;" : "+l"(acc) : "l"(a), "l"(b));
}
__device__ __forceinline__ void unpack2(u64 v, float& lo, float& hi) {
    asm("mov.b64 {%0, %1}, %2;" : "=f"(lo), "=f"(hi) : "l"(v));
}
__device__ __forceinline__ float to_tf32(float x) {
    uint32_t u; asm("cvt.rna.tf32.f32 %0, %1;" : "=r"(u) : "f"(x));
    return __uint_as_float(u);
}
__device__ __forceinline__ void mma8(float* c, const float4& a, const float2& b) {
    asm("mma.sync.aligned.m16n8k8.row.col.f32.tf32.tf32.f32 "
        "{%0,%1,%2,%3}, {%4,%5,%6,%7}, {%8,%9}, {%0,%1,%2,%3};"
        : "+f"(c[0]), "+f"(c[1]), "+f"(c[2]), "+f"(c[3])
        : "r"(__float_as_uint(a.x)), "r"(__float_as_uint(a.y)),
          "r"(__float_as_uint(a.z)), "r"(__float_as_uint(a.w)),
          "r"(__float_as_uint(b.x)), "r"(__float_as_uint(b.y)));
}
__device__ __forceinline__ void storeA(int m, int k, float v) {
    int kstep = k >> 3, kc = k & 7, mr = m & 15;
    int th = ((mr & 7) << 2) | (kc & 3);
    int reg = (mr >> 3) | ((kc >> 2) << 1);
    g_Af[((size_t)(m >> 4) * KS + kstep) * 128 + th * 4 + reg] = to_tf32(v);
}
__device__ __forceinline__ uint32_t smem_u32(const void* p) {
    uint32_t a;
    asm("{ .reg .u64 t; cvta.to.shared.u64 t, %1; cvt.u32.u64 %0, t; }" : "=r"(a) : "l"(p));
    return a;
}
__device__ __forceinline__ void cpa16(uint32_t dst, const void* src) {
    asm volatile("cp.async.ca.shared.global [%0], [%1], 16;" :: "r"(dst), "l"(src));
}
#define CP_COMMIT() asm volatile("cp.async.commit_group;" ::: "memory")
#define CP_WAIT(n)  asm volatile("cp.async.wait_group %0;" :: "n"(n) : "memory")

// ---------------- init + W2 -> tf32 B-fragments (merged) --------------------
__global__ void k_initcvt(const float* __restrict__ W2) {
    int i = blockIdx.x * blockDim.x + threadIdx.x;
    if (i < T) { g_ecnt[i] = 0; g_ncnt[i] = 0; }
    if (i < 3) g_norm3[i] = 0.0f;
    int k = i >> 8, n = i & 255;
    float v = to_tf32(W2[i]);
    int kstep = k >> 3, kc = k & 7;
    int th = ((n & 7) << 2) | (kc & 3);
    int reg = kc >> 2;
    g_Bf[((size_t)kstep * 32 + (n >> 3)) * 64 + th * 2 + reg] = v;
}

// ---------------- scatter into fixed-capacity buckets (packed atomics) ------
#define EBLK (E / 4 / 256)
#define NBLK (NV / 4 / 256)
__global__ void k_scatter(const int* __restrict__ ed, const int* __restrict__ esg,
                          const int* __restrict__ tli, const int* __restrict__ rel,
                          const float* __restrict__ tm, const int* __restrict__ esrc,
                          const int* __restrict__ nsg, const int* __restrict__ hop) {
    int b = blockIdx.x;
    if (b < EBLK) {
        int i = b * 256 + threadIdx.x;
        int4 d4 = ((const int4*)ed)[i];
        int4 s4 = ((const int4*)esg)[i];
        int4 r4 = ((const int4*)rel)[i];
        float4 t4 = ((const float4*)tm)[i];
        int4 sr4 = ((const int4*)esrc)[i];
        int dd[4] = {d4.x, d4.y, d4.z, d4.w};
        int ss[4] = {s4.x, s4.y, s4.z, s4.w};
        int rr[4] = {r4.x, r4.y, r4.z, r4.w};
        float tt[4] = {t4.x, t4.y, t4.z, t4.w};
        int sc[4] = {sr4.x, sr4.y, sr4.z, sr4.w};
#pragma unroll
        for (int q = 0; q < 4; q++) {
            if (dd[q] == __ldg(&tli[ss[q]])) {
                bool inb = (rr[q] < NET);
                int old = atomicAdd(&g_ecnt[ss[q]], inb ? 0x10001 : 1);
                int pos = old & 0xFFFF;
                float t = tt[q];
                unsigned pk = (unsigned)(i * 4 + q) | (inb ? 0x80000000u : 0u);
                float4 mt;
                mt.x = __uint_as_float(pk);
                mt.y = __int_as_float(sc[q]);
                mt.z = expf(-t);
                mt.w = expf(-t * (1.0f / 24.0f));
                g_emeta[(size_t)ss[q] * ECAP + pos] = mt;
            }
        }
    } else {
        int i = (b - EBLK) * 256 + threadIdx.x;
        int4 n4 = ((const int4*)nsg)[i];
        int4 h4 = ((const int4*)hop)[i];
        int nn[4] = {n4.x, n4.y, n4.z, n4.w};
        int hh[4] = {h4.x, h4.y, h4.z, h4.w};
#pragma unroll
        for (int q = 0; q < 4; q++) {
            bool h1 = (hh[q] == 1);
            int old = atomicAdd(&g_ncnt[nn[q]], h1 ? 0x10001 : 1);
            int pos = old & 0xFFFF;
            g_nlist[(size_t)nn[q] * NCAP + pos] =
                (unsigned)(i * 4 + q) | (h1 ? 0x80000000u : 0u);
        }
    }
}

// ---------------- block reduce helpers (128 threads) ------------------------
__device__ __forceinline__ float blk_sum(float v, float* sb) {
#pragma unroll
    for (int o = 16; o > 0; o >>= 1) v += __shfl_xor_sync(0xffffffffu, v, o);
    __syncthreads();
    if ((threadIdx.x & 31) == 0) sb[threadIdx.x >> 5] = v;
    __syncthreads();
    return sb[0] + sb[1] + sb[2] + sb[3];
}
__device__ __forceinline__ float blk_ln(float x, float* sb) {
    float m = blk_sum(x, sb) * (1.0f / 128.0f);
    float d = x - m;
    float v = blk_sum(d * d, sb) * (1.0f / 128.0f);
    return d * rsqrtf(v + 1e-5f);
}

// ---------------- merged aggregation: grid 3T, interleaved b%3 ---------------
__global__ void __launch_bounds__(128, 10) k_agg(const float* __restrict__ edge_repr,
                                                 const float* __restrict__ node_repr,
                                                 const float* __restrict__ W1,
                                                 const float* __restrict__ b1) {
    __shared__ __align__(16) char sbuf[4096 + 8192 + 128];
    float4*   smeta4 = (float4*)sbuf;
    unsigned* smetau = (unsigned*)sbuf;
    float* cmb  = (float*)(sbuf + 4096);
    float* scmb = (float*)(sbuf + 4096 + 8192);
    float* sb   = scmb + 24;

    int b = blockIdx.x;
    int type = b % 3;
    int t = b / 3;
    int tid = threadIdx.x;
    int wid = tid >> 5, lane = tid & 31;
    int c4 = lane << 2;
    int h = tid;

    if (type == 0) {
        int epk = g_ecnt[t];
        int ecount = epk & 0xFFFF;
        const float4* ebase = g_emeta + (size_t)t * ECAP;
        for (int i = tid; i < ecount; i += 128) smeta4[i] = ebase[i];
        __syncthreads();

        float4 v_is = {0,0,0,0}, v_os = {0,0,0,0}, v_il = {0,0,0,0}, v_ol = {0,0,0,0};
        float d_is = 0, d_os = 0, d_il = 0, d_ol = 0, tsum = 0;
#pragma unroll 4
        for (int i = wid; i < ecount; i += 4) {
            float4 mt = smeta4[i];
            unsigned pk = __float_as_uint(mt.x);
            int eidx = pk & 0x7fffffff;
            float sw = mt.z, lw = mt.w;
            float4 er = *(const float4*)(edge_repr + (size_t)eidx * H + c4);
            if (pk & 0x80000000u) {
                v_is.x += sw * er.x; v_is.y += sw * er.y; v_is.z += sw * er.z; v_is.w += sw * er.w;
                v_il.x += lw * er.x; v_il.y += lw * er.y; v_il.z += lw * er.z; v_il.w += lw * er.w;
                d_is += sw; d_il += lw;
            } else {
                v_os.x += sw * er.x; v_os.y += sw * er.y; v_os.z += sw * er.z; v_os.w += sw * er.w;
                v_ol.x += lw * er.x; v_ol.y += lw * er.y; v_ol.z += lw * er.z; v_ol.w += lw * er.w;
                d_os += sw; d_ol += lw;
            }
            tsum += -__logf(sw);
        }

        *(float4*)&cmb[(wid * 4 + 0) * 128 + c4] = v_is;
        *(float4*)&cmb[(wid * 4 + 1) * 128 + c4] = v_os;
        *(float4*)&cmb[(wid * 4 + 2) * 128 + c4] = v_il;
        *(float4*)&cmb[(wid * 4 + 3) * 128 + c4] = v_ol;
        if (lane == 0) {
            scmb[wid * 5 + 0] = d_is; scmb[wid * 5 + 1] = d_os;
            scmb[wid * 5 + 2] = d_il; scmb[wid * 5 + 3] = d_ol;
            scmb[wid * 5 + 4] = tsum;
        }
        __syncthreads();

        float a_is = cmb[0 * 128 + h] + cmb[4 * 128 + h] + cmb[8 * 128 + h] + cmb[12 * 128 + h];
        float a_os = cmb[1 * 128 + h] + cmb[5 * 128 + h] + cmb[9 * 128 + h] + cmb[13 * 128 + h];
        float a_il = cmb[2 * 128 + h] + cmb[6 * 128 + h] + cmb[10 * 128 + h] + cmb[14 * 128 + h];
        float a_ol = cmb[3 * 128 + h] + cmb[7 * 128 + h] + cmb[11 * 128 + h] + cmb[15 * 128 + h];
        d_is = scmb[0] + scmb[5] + scmb[10] + scmb[15];
        d_os = scmb[1] + scmb[6] + scmb[11] + scmb[16];
        d_il = scmb[2] + scmb[7] + scmb[12] + scmb[17];
        d_ol = scmb[3] + scmb[8] + scmb[13] + scmb[18];
        tsum = scmb[4] + scmb[9] + scmb[14] + scmb[19];

        float in_s  = a_is / fmaxf(d_is, 1e-6f);
        float out_s = a_os / fmaxf(d_os, 1e-6f);
        float in_l  = a_il / fmaxf(d_il, 1e-6f);
        float out_l = a_ol / fmaxf(d_ol, 1e-6f);

        float burst = blk_ln(in_s + out_s - in_l - out_l, sb);
        float dirg  = blk_ln(out_l - in_l, sb);
        float asym  = blk_ln(fabsf(dirg), sb);
        float rb    = blk_ln(in_l + out_l, sb);

        float ssd = blk_sum(dirg * dirg, sb);
        if (h == 0) atomicAdd(&g_norm3[2], sqrtf(ssd));

        storeA(t, 0 * H + h, burst);
        storeA(t, 1 * H + h, dirg);
        storeA(t, 4 * H + h, asym);
        storeA(t, 7 * H + h, rb);

        if (h < 32) {
            float cin = (float)(epk >> 16);
            float cnt = (float)ecount;
            float cout = cnt - cin;
            int npk = g_ncnt[t];
            float c1 = (float)(npk >> 16);
            float c2 = (float)(npk & 0xFFFF) - c1;
            float smw = d_is + d_os;
            float lmw = d_il + d_ol;
            float s0 = log1pf(cin), s1 = log1pf(cout), s2 = log1pf(c1), s3 = log1pf(c2);
            float s4 = tsum / fmaxf(cnt, 1e-6f);
            float s5 = smw, s6 = lmw, s7 = smw - lmw;
            float acc = b1[h];
            acc += s0 * W1[0 * 32 + h] + s1 * W1[1 * 32 + h] + s2 * W1[2 * 32 + h] + s3 * W1[3 * 32 + h]
                 + s4 * W1[4 * 32 + h] + s5 * W1[5 * 32 + h] + s6 * W1[6 * 32 + h] + s7 * W1[7 * 32 + h];
            storeA(t, 8 * H + h, gelu_exact(acc));
        }
    } else if (type == 1) {
        int ecount = g_ecnt[t] & 0xFFFF;
        const float4* ebase = g_emeta + (size_t)t * ECAP;
        for (int i = tid; i < ecount; i += 128) smeta4[i] = ebase[i];
        __syncthreads();

        float4 v_hs = {0,0,0,0}, v_hl = {0,0,0,0};
        float smw = 0, lmw = 0;
#pragma unroll 4
        for (int i = wid; i < ecount; i += 4) {
            float4 mt = smeta4[i];
            int src = __float_as_int(mt.y);
            float sw = mt.z, lw = mt.w;
            float4 sr = *(const float4*)(node_repr + (size_t)src * H + c4);
            v_hs.x += sw * sr.x; v_hs.y += sw * sr.y; v_hs.z += sw * sr.z; v_hs.w += sw * sr.w;
            v_hl.x += lw * sr.x; v_hl.y += lw * sr.y; v_hl.z += lw * sr.z; v_hl.w += lw * sr.w;
            smw += sw; lmw += lw;
        }
        *(float4*)&cmb[(wid * 2 + 0) * 128 + c4] = v_hs;
        *(float4*)&cmb[(wid * 2 + 1) * 128 + c4] = v_hl;
        if (lane == 0) { scmb[wid * 2 + 0] = smw; scmb[wid * 2 + 1] = lmw; }
        __syncthreads();

        float a_hs = cmb[0 * 128 + h] + cmb[2 * 128 + h] + cmb[4 * 128 + h] + cmb[6 * 128 + h];
        float a_hl = cmb[1 * 128 + h] + cmb[3 * 128 + h] + cmb[5 * 128 + h] + cmb[7 * 128 + h];
        smw = scmb[0] + scmb[2] + scmb[4] + scmb[6];
        lmw = scmb[1] + scmb[3] + scmb[5] + scmb[7];

        float h1es = a_hs / fmaxf(smw, 1e-6f);
        float h1el = a_hl / fmaxf(lmw, 1e-6f);
        float slg = blk_ln(h1es - h1el, sb);
        float sss = blk_sum(slg * slg, sb);
        if (h == 0) atomicAdd(&g_norm3[1], sqrtf(sss));
        storeA(t, 3 * H + h, slg);
    } else {
        int npk = g_ncnt[t];
        int ncount = npk & 0xFFFF;
        const unsigned* nbase = g_nlist + (size_t)t * NCAP;
        for (int i = tid; i < ncount; i += 128) smetau[i] = nbase[i];
        __syncthreads();

        float4 v_h1 = {0,0,0,0}, v_h2 = {0,0,0,0};
#pragma unroll 4
        for (int i = wid; i < ncount; i += 4) {
            unsigned pk = smetau[i];
            float4 nr = *(const float4*)(node_repr + (size_t)(pk & 0x7fffffff) * H + c4);
            if (pk & 0x80000000u) {
                v_h1.x += nr.x; v_h1.y += nr.y; v_h1.z += nr.z; v_h1.w += nr.w;
            } else {
                v_h2.x += nr.x; v_h2.y += nr.y; v_h2.z += nr.z; v_h2.w += nr.w;
            }
        }
        *(float4*)&cmb[(wid * 2 + 0) * 128 + c4] = v_h1;
        *(float4*)&cmb[(wid * 2 + 1) * 128 + c4] = v_h2;
        __syncthreads();

        float a_h1 = cmb[0 * 128 + h] + cmb[2 * 128 + h] + cmb[4 * 128 + h] + cmb[6 * 128 + h];
        float a_h2 = cmb[1 * 128 + h] + cmb[3 * 128 + h] + cmb[5 * 128 + h] + cmb[7 * 128 + h];
        float c1 = (float)(npk >> 16);
        float c2 = (float)ncount - c1;

        float h1m = a_h1 / fmaxf(c1, 1e-6f);
        float h2m = a_h2 / fmaxf(c2, 1e-6f);

        float hopg = blk_ln(h1m - h2m, sb);
        float h1n  = blk_ln(h1m, sb);
        float h2n  = blk_ln(h2m, sb);

        float ssh = blk_sum(hopg * hopg, sb);
        if (h == 0) atomicAdd(&g_norm3[0], sqrtf(ssh));

        storeA(t, 2 * H + h, hopg);
        storeA(t, 5 * H + h, h1n);
        storeA(t, 6 * H + h, h2n);
    }
}

// ---------------- GEMM1: smem-staged cp.async double-buffered tf32 mma ------
// BM=64 BN=64, 512 thr, grid (64,4). Per 4-kstep group: A 8KB + B 8KB staged
// once into smem; each tile loaded from L2 exactly once per block.
__global__ void __launch_bounds__(512) k_gemm1(const float* __restrict__ b2) {
    __shared__ __align__(16) float sA[2][2048];  // [(mt*4 + u)*128 + i]
    __shared__ __align__(16) float sB[2][2048];  // [(u*8 + nt)*64 + i]
    int tid = threadIdx.x, lane = tid & 31, warp = tid >> 5;
    int wm = warp & 3, wn = warp >> 2;
    int bm = blockIdx.x * 64, bn = blockIdx.y * 64;
    int mt0 = bm >> 4;            // first of 4 m16 tiles for this block
    int ntB = bn >> 3;            // first of 8 n8 tiles for this block

    // copy indices (one float4 per thread per buffer)
    int aflat = tid * 4;
    int a_mt = aflat >> 9;            // 0..3
    int a_u  = (aflat >> 7) & 3;      // 0..3
    int a_i  = aflat & 127;
    int bflat = tid * 4;
    int b_u  = bflat >> 9;            // 0..3
    int b_nt = (bflat >> 6) & 7;      // 0..7
    int b_i  = bflat & 63;

    uint32_t sA_addr[2], sB_addr[2];
#pragma unroll
    for (int s = 0; s < 2; s++) {
        sA_addr[s] = smem_u32(&sA[s][(a_mt * 4 + a_u) * 128 + a_i]);
        sB_addr[s] = smem_u32(&sB[s][(b_u * 8 + b_nt) * 64 + b_i]);
    }

    float c[2][4];
#pragma unroll
    for (int j = 0; j < 2; j++)
#pragma unroll
        for (int r = 0; r < 4; r++) c[j][r] = 0.0f;

    const int NG = KS / 4;  // 33 groups

    // prefetch group 0
    cpa16(sA_addr[0], g_Af + ((size_t)(mt0 + a_mt) * KS + a_u) * 128 + a_i);
    cpa16(sB_addr[0], g_Bf + ((size_t)b_u * 32 + ntB + b_nt) * 64 + b_i);
    CP_COMMIT();

    for (int g = 0; g < NG; g++) {
        int cur = g & 1;
        if (g + 1 < NG) {
            int nxt = cur ^ 1;
            int ks0 = (g + 1) * 4;
            cpa16(sA_addr[nxt], g_Af + ((size_t)(mt0 + a_mt) * KS + ks0 + a_u) * 128 + a_i);
            cpa16(sB_addr[nxt], g_Bf + ((size_t)(ks0 + b_u) * 32 + ntB + b_nt) * 64 + b_i);
            CP_COMMIT();
            CP_WAIT(1);
        } else {
            CP_WAIT(0);
        }
        __syncthreads();

        const float* Ab = &sA[cur][(wm * 4) * 128 + lane * 4];
        const float* Bb = &sB[cur][(wn * 2) * 64 + lane * 2];
#pragma unroll
        for (int u = 0; u < 4; u++) {
            float4 a0 = *(const float4*)(Ab + u * 128);
            float2 b0 = *(const float2*)(Bb + u * 512);
            float2 b1v = *(const float2*)(Bb + u * 512 + 64);
            mma8(c[0], a0, b0);
            mma8(c[1], a0, b1v);
        }
        __syncthreads();
    }

    int r0 = bm + wm * 16 + (lane >> 2);
#pragma unroll
    for (int j = 0; j < 2; j++) {
        int cc = bn + wn * 16 + j * 8 + (lane & 3) * 2;
        float bx = b2[cc], by = b2[cc + 1];
        float2 lo, hi;
        lo.x = gelu_exact(c[j][0] + bx);
        lo.y = gelu_exact(c[j][1] + by);
        hi.x = gelu_exact(c[j][2] + bx);
        hi.y = gelu_exact(c[j][3] + by);
        *(float2*)(g_hidden + (size_t)r0 * HD + cc) = lo;
        *(float2*)(g_hidden + (size_t)(r0 + 8) * HD + cc) = hi;
    }
}

// ---------------- GEMM2: [T,256] @ [256,128] + bias + 0.25*tanh + norms -----
__global__ void __launch_bounds__(256) k_gemm2(const float* __restrict__ W3,
                                               const float* __restrict__ b3,
                                               float* __restrict__ out) {
    __shared__ float hs[16 * 256];
    int tid = threadIdx.x;
    int t0 = blockIdx.x * 16;
    if (blockIdx.x == 0 && tid < 3)
        out[(size_t)T * H + tid] = g_norm3[tid] * (1.0f / (float)T);
    for (int i = tid; i < 16 * 256; i += 256)
        hs[i] = g_hidden[(size_t)t0 * 256 + i];
    __syncthreads();
    int n = tid & 127;
    int half = tid >> 7;
    const float* hp = hs + half * 8 * 256;
    u64 acc2[8];
#pragma unroll
    for (int r = 0; r < 8; r++) acc2[r] = 0ull;
    for (int k = 0; k < 256; k += 4) {
        float w0 = W3[(k + 0) * 128 + n];
        float w1 = W3[(k + 1) * 128 + n];
        float w2 = W3[(k + 2) * 128 + n];
        float w3v = W3[(k + 3) * 128 + n];
        u64 w01 = pack2(w0, w1);
        u64 w23 = pack2(w2, w3v);
#pragma unroll
        for (int r = 0; r < 8; r++) {
            ulonglong2 hv = *(const ulonglong2*)&hp[r * 256 + k];
            fma2(acc2[r], hv.x, w01);
            fma2(acc2[r], hv.y, w23);
        }
    }
    float bias = b3[n];
#pragma unroll
    for (int r = 0; r < 8; r++) {
        float lo, hi;
        unpack2(acc2[r], lo, hi);
        out[(size_t)(t0 + half * 8 + r) * 128 + n] = 0.25f * tanhf(lo + hi + bias);
    }
}

// ---------------- launcher --------------------------------------------------
extern "C" void kernel_launch(void* const* d_in, const int* in_sizes, int n_in,
                              void* d_out, int out_size) {
    const float* node_repr = (const float*)d_in[0];
    const float* edge_repr = (const float*)d_in[1];
    const int*   edge_src  = (const int*)d_in[2];
    const int*   edge_dst  = (const int*)d_in[3];
    const int*   rel_ids   = (const int*)d_in[4];
    const float* etime     = (const float*)d_in[5];
    const int*   tli       = (const int*)d_in[6];
    const int*   nsg       = (const int*)d_in[7];
    const int*   esg       = (const int*)d_in[8];
    const int*   hop       = (const int*)d_in[9];
    const float* W1 = (const float*)d_in[10];
    const float* b1 = (const float*)d_in[11];
    const float* W2 = (const float*)d_in[12];
    const float* b2 = (const float*)d_in[13];
    const float* W3 = (const float*)d_in[14];
    const float* b3 = (const float*)d_in[15];
    float* out = (float*)d_out;

    k_initcvt<<<FD * HD / 256, 256>>>(W2);
    k_scatter<<<EBLK + NBLK, 256>>>(edge_dst, esg, tli, rel_ids, etime, edge_src, nsg, hop);
    k_agg<<<3 * T, 128>>>(edge_repr, node_repr, W1, b1);
    k_gemm1<<<dim3(64, 4), 512>>>(b2);
    k_gemm2<<<T / 16, 256>>>(W3, b3, out);
}

// round 16
// speedup vs baseline: 1.2583x; 1.0115x over previous
#include <cuda_runtime.h>
#include <cuda_bf16.h>
#include <cstdint>

#define H 128
#define E 1048576
#define NV 262144
#define T 4096
#define NET 8
#define FD 1056   // 8*H + 32
#define HD 256    // 2*H
#define KS 132    // FD / 8 k-steps
#define ECAP 256
#define NCAP 256

// ---------------- scratch ---------------------------------------------------
__device__ int g_ecnt[T];   // low 16: edge count, high 16: inbound count
__device__ int g_ncnt[T];   // low 16: node count, high 16: hop1 count
__device__ float4   g_emeta[(size_t)T * ECAP];
__device__ unsigned g_nlist[(size_t)T * NCAP];
__device__ float g_Af[(size_t)(T / 16) * KS * 128];
__device__ float g_Bf[(size_t)KS * 32 * 64];
__device__ float g_hidden[(size_t)T * HD];
__device__ float g_norm3[3];

typedef unsigned long long u64;

__device__ __forceinline__ float gelu_exact(float x) {
    return 0.5f * x * (1.0f + erff(x * 0.7071067811865476f));
}
__device__ __forceinline__ u64 pack2(float lo, float hi) {
    u64 r; asm("mov.b64 %0, {%1, %2};" : "=l"(r) : "f"(lo), "f"(hi)); return r;
}
__device__ __forceinline__ void fma2(u64& acc, u64 a, u64 b) {
    asm("fma.rn.f32x2 %0, %1, %2, %0;" : "+l"(acc) : "l"(a), "l"(b));
}
__device__ __forceinline__ void unpack2(u64 v, float& lo, float& hi) {
    asm("mov.b64 {%0, %1}, %2;" : "=f"(lo), "=f"(hi) : "l"(v));
}
__device__ __forceinline__ float to_tf32(float x) {
    uint32_t u; asm("cvt.rna.tf32.f32 %0, %1;" : "=r"(u) : "f"(x));
    return __uint_as_float(u);
}
__device__ __forceinline__ void mma8(float* c, const float4& a, const float2& b) {
    asm("mma.sync.aligned.m16n8k8.row.col.f32.tf32.tf32.f32 "
        "{%0,%1,%2,%3}, {%4,%5,%6,%7}, {%8,%9}, {%0,%1,%2,%3};"
        : "+f"(c[0]), "+f"(c[1]), "+f"(c[2]), "+f"(c[3])
        : "r"(__float_as_uint(a.x)), "r"(__float_as_uint(a.y)),
          "r"(__float_as_uint(a.z)), "r"(__float_as_uint(a.w)),
          "r"(__float_as_uint(b.x)), "r"(__float_as_uint(b.y)));
}
__device__ __forceinline__ void storeA(int m, int k, float v) {
    int kstep = k >> 3, kc = k & 7, mr = m & 15;
    int th = ((mr & 7) << 2) | (kc & 3);
    int reg = (mr >> 3) | ((kc >> 2) << 1);
    g_Af[((size_t)(m >> 4) * KS + kstep) * 128 + th * 4 + reg] = to_tf32(v);
}
__device__ __forceinline__ uint32_t smem_u32(const void* p) {
    uint32_t a;
    asm("{ .reg .u64 t; cvta.to.shared.u64 t, %1; cvt.u32.u64 %0, t; }" : "=r"(a) : "l"(p));
    return a;
}
__device__ __forceinline__ void cpa16(uint32_t dst, const void* src) {
    asm volatile("cp.async.ca.shared.global [%0], [%1], 16;" :: "r"(dst), "l"(src));
}
#define CP_COMMIT() asm volatile("cp.async.commit_group;" ::: "memory")
#define CP_WAIT(n)  asm volatile("cp.async.wait_group %0;" :: "n"(n) : "memory")

// ---------------- init + W2 -> tf32 B-fragments (merged) --------------------
__global__ void k_initcvt(const float* __restrict__ W2) {
    int i = blockIdx.x * blockDim.x + threadIdx.x;
    if (i < T) { g_ecnt[i] = 0; g_ncnt[i] = 0; }
    if (i < 3) g_norm3[i] = 0.0f;
    int k = i >> 8, n = i & 255;
    float v = to_tf32(W2[i]);
    int kstep = k >> 3, kc = k & 7;
    int th = ((n & 7) << 2) | (kc & 3);
    int reg = kc >> 2;
    g_Bf[((size_t)kstep * 32 + (n >> 3)) * 64 + th * 2 + reg] = v;
}

// ---------------- scatter into fixed-capacity buckets (packed atomics) ------
#define EBLK (E / 4 / 256)
#define NBLK (NV / 4 / 256)
__global__ void k_scatter(const int* __restrict__ ed, const int* __restrict__ esg,
                          const int* __restrict__ tli, const int* __restrict__ rel,
                          const float* __restrict__ tm, const int* __restrict__ esrc,
                          const int* __restrict__ nsg, const int* __restrict__ hop) {
    int b = blockIdx.x;
    if (b < EBLK) {
        int i = b * 256 + threadIdx.x;
        int4 d4 = ((const int4*)ed)[i];
        int4 s4 = ((const int4*)esg)[i];
        int4 r4 = ((const int4*)rel)[i];
        float4 t4 = ((const float4*)tm)[i];
        int4 sr4 = ((const int4*)esrc)[i];
        int dd[4] = {d4.x, d4.y, d4.z, d4.w};
        int ss[4] = {s4.x, s4.y, s4.z, s4.w};
        int rr[4] = {r4.x, r4.y, r4.z, r4.w};
        float tt[4] = {t4.x, t4.y, t4.z, t4.w};
        int sc[4] = {sr4.x, sr4.y, sr4.z, sr4.w};
#pragma unroll
        for (int q = 0; q < 4; q++) {
            if (dd[q] == __ldg(&tli[ss[q]])) {
                bool inb = (rr[q] < NET);
                int old = atomicAdd(&g_ecnt[ss[q]], inb ? 0x10001 : 1);
                int pos = old & 0xFFFF;
                float t = tt[q];
                unsigned pk = (unsigned)(i * 4 + q) | (inb ? 0x80000000u : 0u);
                float4 mt;
                mt.x = __uint_as_float(pk);
                mt.y = __int_as_float(sc[q]);
                mt.z = expf(-t);
                mt.w = expf(-t * (1.0f / 24.0f));
                g_emeta[(size_t)ss[q] * ECAP + pos] = mt;
            }
        }
    } else {
        int i = (b - EBLK) * 256 + threadIdx.x;
        int4 n4 = ((const int4*)nsg)[i];
        int4 h4 = ((const int4*)hop)[i];
        int nn[4] = {n4.x, n4.y, n4.z, n4.w};
        int hh[4] = {h4.x, h4.y, h4.z, h4.w};
#pragma unroll
        for (int q = 0; q < 4; q++) {
            bool h1 = (hh[q] == 1);
            int old = atomicAdd(&g_ncnt[nn[q]], h1 ? 0x10001 : 1);
            int pos = old & 0xFFFF;
            g_nlist[(size_t)nn[q] * NCAP + pos] =
                (unsigned)(i * 4 + q) | (h1 ? 0x80000000u : 0u);
        }
    }
}

// ---------------- block reduce helpers (128 threads) ------------------------
__device__ __forceinline__ float blk_sum(float v, float* sb) {
#pragma unroll
    for (int o = 16; o > 0; o >>= 1) v += __shfl_xor_sync(0xffffffffu, v, o);
    __syncthreads();
    if ((threadIdx.x & 31) == 0) sb[threadIdx.x >> 5] = v;
    __syncthreads();
    return sb[0] + sb[1] + sb[2] + sb[3];
}
__device__ __forceinline__ float blk_ln(float x, float* sb) {
    float m = blk_sum(x, sb) * (1.0f / 128.0f);
    float d = x - m;
    float v = blk_sum(d * d, sb) * (1.0f / 128.0f);
    return d * rsqrtf(v + 1e-5f);
}

// ---------------- merged aggregation: grid 3T, interleaved b%3 ---------------
__global__ void __launch_bounds__(128, 10) k_agg(const float* __restrict__ edge_repr,
                                                 const float* __restrict__ node_repr,
                                                 const float* __restrict__ W1,
                                                 const float* __restrict__ b1) {
    __shared__ __align__(16) char sbuf[4096 + 8192 + 128];
    float4*   smeta4 = (float4*)sbuf;
    unsigned* smetau = (unsigned*)sbuf;
    float* cmb  = (float*)(sbuf + 4096);
    float* scmb = (float*)(sbuf + 4096 + 8192);
    float* sb   = scmb + 24;

    int b = blockIdx.x;
    int type = b % 3;
    int t = b / 3;
    int tid = threadIdx.x;
    int wid = tid >> 5, lane = tid & 31;
    int c4 = lane << 2;
    int h = tid;

    if (type == 0) {
        int epk = g_ecnt[t];
        int ecount = epk & 0xFFFF;
        const float4* ebase = g_emeta + (size_t)t * ECAP;
        for (int i = tid; i < ecount; i += 128) smeta4[i] = ebase[i];
        __syncthreads();

        float4 v_is = {0,0,0,0}, v_os = {0,0,0,0}, v_il = {0,0,0,0}, v_ol = {0,0,0,0};
        float d_is = 0, d_os = 0, d_il = 0, d_ol = 0, tsum = 0;
#pragma unroll 4
        for (int i = wid; i < ecount; i += 4) {
            float4 mt = smeta4[i];
            unsigned pk = __float_as_uint(mt.x);
            int eidx = pk & 0x7fffffff;
            float sw = mt.z, lw = mt.w;
            float4 er = *(const float4*)(edge_repr + (size_t)eidx * H + c4);
            if (pk & 0x80000000u) {
                v_is.x += sw * er.x; v_is.y += sw * er.y; v_is.z += sw * er.z; v_is.w += sw * er.w;
                v_il.x += lw * er.x; v_il.y += lw * er.y; v_il.z += lw * er.z; v_il.w += lw * er.w;
                d_is += sw; d_il += lw;
            } else {
                v_os.x += sw * er.x; v_os.y += sw * er.y; v_os.z += sw * er.z; v_os.w += sw * er.w;
                v_ol.x += lw * er.x; v_ol.y += lw * er.y; v_ol.z += lw * er.z; v_ol.w += lw * er.w;
                d_os += sw; d_ol += lw;
            }
            tsum += -__logf(sw);
        }

        *(float4*)&cmb[(wid * 4 + 0) * 128 + c4] = v_is;
        *(float4*)&cmb[(wid * 4 + 1) * 128 + c4] = v_os;
        *(float4*)&cmb[(wid * 4 + 2) * 128 + c4] = v_il;
        *(float4*)&cmb[(wid * 4 + 3) * 128 + c4] = v_ol;
        if (lane == 0) {
            scmb[wid * 5 + 0] = d_is; scmb[wid * 5 + 1] = d_os;
            scmb[wid * 5 + 2] = d_il; scmb[wid * 5 + 3] = d_ol;
            scmb[wid * 5 + 4] = tsum;
        }
        __syncthreads();

        float a_is = cmb[0 * 128 + h] + cmb[4 * 128 + h] + cmb[8 * 128 + h] + cmb[12 * 128 + h];
        float a_os = cmb[1 * 128 + h] + cmb[5 * 128 + h] + cmb[9 * 128 + h] + cmb[13 * 128 + h];
        float a_il = cmb[2 * 128 + h] + cmb[6 * 128 + h] + cmb[10 * 128 + h] + cmb[14 * 128 + h];
        float a_ol = cmb[3 * 128 + h] + cmb[7 * 128 + h] + cmb[11 * 128 + h] + cmb[15 * 128 + h];
        d_is = scmb[0] + scmb[5] + scmb[10] + scmb[15];
        d_os = scmb[1] + scmb[6] + scmb[11] + scmb[16];
        d_il = scmb[2] + scmb[7] + scmb[12] + scmb[17];
        d_ol = scmb[3] + scmb[8] + scmb[13] + scmb[18];
        tsum = scmb[4] + scmb[9] + scmb[14] + scmb[19];

        float in_s  = a_is / fmaxf(d_is, 1e-6f);
        float out_s = a_os / fmaxf(d_os, 1e-6f);
        float in_l  = a_il / fmaxf(d_il, 1e-6f);
        float out_l = a_ol / fmaxf(d_ol, 1e-6f);

        float burst = blk_ln(in_s + out_s - in_l - out_l, sb);
        float dirg  = blk_ln(out_l - in_l, sb);
        float asym  = blk_ln(fabsf(dirg), sb);
        float rb    = blk_ln(in_l + out_l, sb);

        float ssd = blk_sum(dirg * dirg, sb);
        if (h == 0) atomicAdd(&g_norm3[2], sqrtf(ssd));

        storeA(t, 0 * H + h, burst);
        storeA(t, 1 * H + h, dirg);
        storeA(t, 4 * H + h, asym);
        storeA(t, 7 * H + h, rb);

        if (h < 32) {
            float cin = (float)(epk >> 16);
            float cnt = (float)ecount;
            float cout = cnt - cin;
            int npk = g_ncnt[t];
            float c1 = (float)(npk >> 16);
            float c2 = (float)(npk & 0xFFFF) - c1;
            float smw = d_is + d_os;
            float lmw = d_il + d_ol;
            float s0 = log1pf(cin), s1 = log1pf(cout), s2 = log1pf(c1), s3 = log1pf(c2);
            float s4 = tsum / fmaxf(cnt, 1e-6f);
            float s5 = smw, s6 = lmw, s7 = smw - lmw;
            float acc = b1[h];
            acc += s0 * W1[0 * 32 + h] + s1 * W1[1 * 32 + h] + s2 * W1[2 * 32 + h] + s3 * W1[3 * 32 + h]
                 + s4 * W1[4 * 32 + h] + s5 * W1[5 * 32 + h] + s6 * W1[6 * 32 + h] + s7 * W1[7 * 32 + h];
            storeA(t, 8 * H + h, gelu_exact(acc));
        }
    } else if (type == 1) {
        int ecount = g_ecnt[t] & 0xFFFF;
        const float4* ebase = g_emeta + (size_t)t * ECAP;
        for (int i = tid; i < ecount; i += 128) smeta4[i] = ebase[i];
        __syncthreads();

        float4 v_hs = {0,0,0,0}, v_hl = {0,0,0,0};
        float smw = 0, lmw = 0;
#pragma unroll 4
        for (int i = wid; i < ecount; i += 4) {
            float4 mt = smeta4[i];
            int src = __float_as_int(mt.y);
            float sw = mt.z, lw = mt.w;
            float4 sr = *(const float4*)(node_repr + (size_t)src * H + c4);
            v_hs.x += sw * sr.x; v_hs.y += sw * sr.y; v_hs.z += sw * sr.z; v_hs.w += sw * sr.w;
            v_hl.x += lw * sr.x; v_hl.y += lw * sr.y; v_hl.z += lw * sr.z; v_hl.w += lw * sr.w;
            smw += sw; lmw += lw;
        }
        *(float4*)&cmb[(wid * 2 + 0) * 128 + c4] = v_hs;
        *(float4*)&cmb[(wid * 2 + 1) * 128 + c4] = v_hl;
        if (lane == 0) { scmb[wid * 2 + 0] = smw; scmb[wid * 2 + 1] = lmw; }
        __syncthreads();

        float a_hs = cmb[0 * 128 + h] + cmb[2 * 128 + h] + cmb[4 * 128 + h] + cmb[6 * 128 + h];
        float a_hl = cmb[1 * 128 + h] + cmb[3 * 128 + h] + cmb[5 * 128 + h] + cmb[7 * 128 + h];
        smw = scmb[0] + scmb[2] + scmb[4] + scmb[6];
        lmw = scmb[1] + scmb[3] + scmb[5] + scmb[7];

        float h1es = a_hs / fmaxf(smw, 1e-6f);
        float h1el = a_hl / fmaxf(lmw, 1e-6f);
        float slg = blk_ln(h1es - h1el, sb);
        float sss = blk_sum(slg * slg, sb);
        if (h == 0) atomicAdd(&g_norm3[1], sqrtf(sss));
        storeA(t, 3 * H + h, slg);
    } else {
        int npk = g_ncnt[t];
        int ncount = npk & 0xFFFF;
        const unsigned* nbase = g_nlist + (size_t)t * NCAP;
        for (int i = tid; i < ncount; i += 128) smetau[i] = nbase[i];
        __syncthreads();

        float4 v_h1 = {0,0,0,0}, v_h2 = {0,0,0,0};
#pragma unroll 4
        for (int i = wid; i < ncount; i += 4) {
            unsigned pk = smetau[i];
            float4 nr = *(const float4*)(node_repr + (size_t)(pk & 0x7fffffff) * H + c4);
            if (pk & 0x80000000u) {
                v_h1.x += nr.x; v_h1.y += nr.y; v_h1.z += nr.z; v_h1.w += nr.w;
            } else {
                v_h2.x += nr.x; v_h2.y += nr.y; v_h2.z += nr.z; v_h2.w += nr.w;
            }
        }
        *(float4*)&cmb[(wid * 2 + 0) * 128 + c4] = v_h1;
        *(float4*)&cmb[(wid * 2 + 1) * 128 + c4] = v_h2;
        __syncthreads();

        float a_h1 = cmb[0 * 128 + h] + cmb[2 * 128 + h] + cmb[4 * 128 + h] + cmb[6 * 128 + h];
        float a_h2 = cmb[1 * 128 + h] + cmb[3 * 128 + h] + cmb[5 * 128 + h] + cmb[7 * 128 + h];
        float c1 = (float)(npk >> 16);
        float c2 = (float)ncount - c1;

        float h1m = a_h1 / fmaxf(c1, 1e-6f);
        float h2m = a_h2 / fmaxf(c2, 1e-6f);

        float hopg = blk_ln(h1m - h2m, sb);
        float h1n  = blk_ln(h1m, sb);
        float h2n  = blk_ln(h2m, sb);

        float ssh = blk_sum(hopg * hopg, sb);
        if (h == 0) atomicAdd(&g_norm3[0], sqrtf(ssh));

        storeA(t, 2 * H + h, hopg);
        storeA(t, 5 * H + h, h1n);
        storeA(t, 6 * H + h, h2n);
    }
}

// ---------------- GEMM1: smem-staged, warp tile 32x32 (reg reuse) -----------
// BM=64 BN=128, 256 threads = 8 warps (2m x 4n), grid (64,2) = 128 blocks.
// Per 4-kstep group: stage A 8KB + B 16KB; each warp: per u 2 A + 4 B loads
// -> 8 mma (187B LDS per mma, 2.7x less crossbar than 16x16 tile).
__global__ void __launch_bounds__(256) k_gemm1(const float* __restrict__ b2) {
    __shared__ __align__(16) float sA[2][2048];  // [(mt*4 + u)*128 + i]
    __shared__ __align__(16) float sB[2][4096];  // [(u*16 + nt)*64 + i]
    int tid = threadIdx.x, lane = tid & 31, warp = tid >> 5;
    int wm = warp & 1, wn = warp >> 1;           // wm 0..1, wn 0..3
    int bm = blockIdx.x * 64, bn = blockIdx.y * 128;
    int mt0 = bm >> 4;            // first of 4 m16 tiles
    int ntB = bn >> 3;            // first of 16 n8 tiles

    // A copy: 2 float4 per thread per buffer
    int a_mt[2], a_u[2], a_i[2];
#pragma unroll
    for (int q = 0; q < 2; q++) {
        int flat = (tid + q * 256) * 4;
        a_mt[q] = flat >> 9;
        a_u[q]  = (flat >> 7) & 3;
        a_i[q]  = flat & 127;
    }
    // B copy: 4 float4 per thread per buffer
    int b_u[4], b_nt[4], b_i[4];
#pragma unroll
    for (int q = 0; q < 4; q++) {
        int flat = (tid + q * 256) * 4;
        b_u[q]  = flat >> 10;
        b_nt[q] = (flat >> 6) & 15;
        b_i[q]  = flat & 63;
    }
    uint32_t sA_addr[2][2], sB_addr[2][4];
#pragma unroll
    for (int s = 0; s < 2; s++) {
#pragma unroll
        for (int q = 0; q < 2; q++)
            sA_addr[s][q] = smem_u32(&sA[s][(a_mt[q] * 4 + a_u[q]) * 128 + a_i[q]]);
#pragma unroll
        for (int q = 0; q < 4; q++)
            sB_addr[s][q] = smem_u32(&sB[s][(b_u[q] * 16 + b_nt[q]) * 64 + b_i[q]]);
    }

    float c[2][4][4];
#pragma unroll
    for (int mi = 0; mi < 2; mi++)
#pragma unroll
        for (int j = 0; j < 4; j++)
#pragma unroll
            for (int r = 0; r < 4; r++) c[mi][j][r] = 0.0f;

    const int NG = KS / 4;  // 33 groups

    // prefetch group 0
#pragma unroll
    for (int q = 0; q < 2; q++)
        cpa16(sA_addr[0][q], g_Af + ((size_t)(mt0 + a_mt[q]) * KS + a_u[q]) * 128 + a_i[q]);
#pragma unroll
    for (int q = 0; q < 4; q++)
        cpa16(sB_addr[0][q], g_Bf + ((size_t)b_u[q] * 32 + ntB + b_nt[q]) * 64 + b_i[q]);
    CP_COMMIT();

    for (int g = 0; g < NG; g++) {
        int cur = g & 1;
        if (g + 1 < NG) {
            int nxt = cur ^ 1;
            int ks0 = (g + 1) * 4;
#pragma unroll
            for (int q = 0; q < 2; q++)
                cpa16(sA_addr[nxt][q],
                      g_Af + ((size_t)(mt0 + a_mt[q]) * KS + ks0 + a_u[q]) * 128 + a_i[q]);
#pragma unroll
            for (int q = 0; q < 4; q++)
                cpa16(sB_addr[nxt][q],
                      g_Bf + ((size_t)(ks0 + b_u[q]) * 32 + ntB + b_nt[q]) * 64 + b_i[q]);
            CP_COMMIT();
            CP_WAIT(1);
        } else {
            CP_WAIT(0);
        }
        __syncthreads();

        const float* Ab = &sA[cur][(wm * 2 * 4) * 128 + lane * 4];
        const float* Bb = &sB[cur][(wn * 4) * 64 + lane * 2];
#pragma unroll
        for (int u = 0; u < 4; u++) {
            float4 a0 = *(const float4*)(Ab + u * 128);
            float4 a1 = *(const float4*)(Ab + (4 + u) * 128);
            float2 bv[4];
#pragma unroll
            for (int j = 0; j < 4; j++)
                bv[j] = *(const float2*)(Bb + (u * 16 + j) * 64);
#pragma unroll
            for (int j = 0; j < 4; j++) {
                mma8(c[0][j], a0, bv[j]);
                mma8(c[1][j], a1, bv[j]);
            }
        }
        __syncthreads();
    }

#pragma unroll
    for (int mi = 0; mi < 2; mi++) {
        int r0 = bm + wm * 32 + mi * 16 + (lane >> 2);
#pragma unroll
        for (int j = 0; j < 4; j++) {
            int cc = bn + wn * 32 + j * 8 + (lane & 3) * 2;
            float bx = b2[cc], by = b2[cc + 1];
            float2 lo, hi;
            lo.x = gelu_exact(c[mi][j][0] + bx);
            lo.y = gelu_exact(c[mi][j][1] + by);
            hi.x = gelu_exact(c[mi][j][2] + bx);
            hi.y = gelu_exact(c[mi][j][3] + by);
            *(float2*)(g_hidden + (size_t)r0 * HD + cc) = lo;
            *(float2*)(g_hidden + (size_t)(r0 + 8) * HD + cc) = hi;
        }
    }
}

// ---------------- GEMM2: [T,256] @ [256,128] + bias + 0.25*tanh + norms -----
__global__ void __launch_bounds__(256) k_gemm2(const float* __restrict__ W3,
                                               const float* __restrict__ b3,
                                               float* __restrict__ out) {
    __shared__ float hs[16 * 256];
    int tid = threadIdx.x;
    int t0 = blockIdx.x * 16;
    if (blockIdx.x == 0 && tid < 3)
        out[(size_t)T * H + tid] = g_norm3[tid] * (1.0f / (float)T);
    for (int i = tid; i < 16 * 256; i += 256)
        hs[i] = g_hidden[(size_t)t0 * 256 + i];
    __syncthreads();
    int n = tid & 127;
    int half = tid >> 7;
    const float* hp = hs + half * 8 * 256;
    u64 acc2[8];
#pragma unroll
    for (int r = 0; r < 8; r++) acc2[r] = 0ull;
    for (int k = 0; k < 256; k += 4) {
        float w0 = W3[(k + 0) * 128 + n];
        float w1 = W3[(k + 1) * 128 + n];
        float w2 = W3[(k + 2) * 128 + n];
        float w3v = W3[(k + 3) * 128 + n];
        u64 w01 = pack2(w0, w1);
        u64 w23 = pack2(w2, w3v);
#pragma unroll
        for (int r = 0; r < 8; r++) {
            ulonglong2 hv = *(const ulonglong2*)&hp[r * 256 + k];
            fma2(acc2[r], hv.x, w01);
            fma2(acc2[r], hv.y, w23);
        }
    }
    float bias = b3[n];
#pragma unroll
    for (int r = 0; r < 8; r++) {
        float lo, hi;
        unpack2(acc2[r], lo, hi);
        out[(size_t)(t0 + half * 8 + r) * 128 + n] = 0.25f * tanhf(lo + hi + bias);
    }
}

// ---------------- launcher --------------------------------------------------
extern "C" void kernel_launch(void* const* d_in, const int* in_sizes, int n_in,
                              void* d_out, int out_size) {
    const float* node_repr = (const float*)d_in[0];
    const float* edge_repr = (const float*)d_in[1];
    const int*   edge_src  = (const int*)d_in[2];
    const int*   edge_dst  = (const int*)d_in[3];
    const int*   rel_ids   = (const int*)d_in[4];
    const float* etime     = (const float*)d_in[5];
    const int*   tli       = (const int*)d_in[6];
    const int*   nsg       = (const int*)d_in[7];
    const int*   esg       = (const int*)d_in[8];
    const int*   hop       = (const int*)d_in[9];
    const float* W1 = (const float*)d_in[10];
    const float* b1 = (const float*)d_in[11];
    const float* W2 = (const float*)d_in[12];
    const float* b2 = (const float*)d_in[13];
    const float* W3 = (const float*)d_in[14];
    const float* b3 = (const float*)d_in[15];
    float* out = (float*)d_out;

    k_initcvt<<<FD * HD / 256, 256>>>(W2);
    k_scatter<<<EBLK + NBLK, 256>>>(edge_dst, esg, tli, rel_ids, etime, edge_src, nsg, hop);
    k_agg<<<3 * T, 128>>>(edge_repr, node_repr, W1, b1);
    k_gemm1<<<dim3(64, 2), 256>>>(b2);
    k_gemm2<<<T / 16, 256>>>(W3, b3, out);
}

// round 17
// speedup vs baseline: 1.2629x; 1.0036x over previous
#include <cuda_runtime.h>
#include <cuda_bf16.h>
#include <cstdint>

#define H 128
#define E 1048576
#define NV 262144
#define T 4096
#define NET 8
#define FD 1056   // 8*H + 32
#define HD 256    // 2*H
#define KS 132    // FD / 8 k-steps
#define ECAP 256
#define NCAP 256

// ---------------- scratch ---------------------------------------------------
__device__ int g_ecnt[T];   // low 16: edge count, high 16: inbound count
__device__ int g_ncnt[T];   // low 16: node count, high 16: hop1 count
__device__ float4   g_emeta[(size_t)T * ECAP];
__device__ unsigned g_nlist[(size_t)T * NCAP];
__device__ float g_Af[(size_t)(T / 16) * KS * 128];
__device__ float g_Bf[(size_t)KS * 32 * 64];
__device__ float g_hidden[(size_t)T * HD];
__device__ float g_norm3[3];

typedef unsigned long long u64;

__device__ __forceinline__ float gelu_exact(float x) {
    return 0.5f * x * (1.0f + erff(x * 0.7071067811865476f));
}
__device__ __forceinline__ u64 pack2(float lo, float hi) {
    u64 r; asm("mov.b64 %0, {%1, %2};" : "=l"(r) : "f"(lo), "f"(hi)); return r;
}
__device__ __forceinline__ void fma2(u64& acc, u64 a, u64 b) {
    asm("fma.rn.f32x2 %0, %1, %2, %0;" : "+l"(acc) : "l"(a), "l"(b));
}
__device__ __forceinline__ void unpack2(u64 v, float& lo, float& hi) {
    asm("mov.b64 {%0, %1}, %2;" : "=f"(lo), "=f"(hi) : "l"(v));
}
__device__ __forceinline__ float to_tf32(float x) {
    uint32_t u; asm("cvt.rna.tf32.f32 %0, %1;" : "=r"(u) : "f"(x));
    return __uint_as_float(u);
}
__device__ __forceinline__ void mma8(float* c, const float4& a, const float2& b) {
    asm("mma.sync.aligned.m16n8k8.row.col.f32.tf32.tf32.f32 "
        "{%0,%1,%2,%3}, {%4,%5,%6,%7}, {%8,%9}, {%0,%1,%2,%3};"
        : "+f"(c[0]), "+f"(c[1]), "+f"(c[2]), "+f"(c[3])
        : "r"(__float_as_uint(a.x)), "r"(__float_as_uint(a.y)),
          "r"(__float_as_uint(a.z)), "r"(__float_as_uint(a.w)),
          "r"(__float_as_uint(b.x)), "r"(__float_as_uint(b.y)));
}
__device__ __forceinline__ void storeA(int m, int k, float v) {
    int kstep = k >> 3, kc = k & 7, mr = m & 15;
    int th = ((mr & 7) << 2) | (kc & 3);
    int reg = (mr >> 3) | ((kc >> 2) << 1);
    g_Af[((size_t)(m >> 4) * KS + kstep) * 128 + th * 4 + reg] = to_tf32(v);
}
__device__ __forceinline__ uint32_t smem_u32(const void* p) {
    uint32_t a;
    asm("{ .reg .u64 t; cvta.to.shared.u64 t, %1; cvt.u32.u64 %0, t; }" : "=r"(a) : "l"(p));
    return a;
}
__device__ __forceinline__ void cpa16(uint32_t dst, const void* src) {
    asm volatile("cp.async.ca.shared.global [%0], [%1], 16;" :: "r"(dst), "l"(src));
}
#define CP_COMMIT() asm volatile("cp.async.commit_group;" ::: "memory")
#define CP_WAIT(n)  asm volatile("cp.async.wait_group %0;" :: "n"(n) : "memory")

// ---------------- init + W2 -> tf32 B-fragments (merged) --------------------
__global__ void k_initcvt(const float* __restrict__ W2) {
    int i = blockIdx.x * blockDim.x + threadIdx.x;
    if (i < T) { g_ecnt[i] = 0; g_ncnt[i] = 0; }
    if (i < 3) g_norm3[i] = 0.0f;
    int k = i >> 8, n = i & 255;
    float v = to_tf32(W2[i]);
    int kstep = k >> 3, kc = k & 7;
    int th = ((n & 7) << 2) | (kc & 3);
    int reg = kc >> 2;
    g_Bf[((size_t)kstep * 32 + (n >> 3)) * 64 + th * 2 + reg] = v;
}

// ---------------- scatter into fixed-capacity buckets (packed atomics) ------
#define EBLK (E / 4 / 256)
#define NBLK (NV / 4 / 256)
__global__ void k_scatter(const int* __restrict__ ed, const int* __restrict__ esg,
                          const int* __restrict__ tli, const int* __restrict__ rel,
                          const float* __restrict__ tm, const int* __restrict__ esrc,
                          const int* __restrict__ nsg, const int* __restrict__ hop) {
    int b = blockIdx.x;
    if (b < EBLK) {
        int i = b * 256 + threadIdx.x;
        int4 d4 = ((const int4*)ed)[i];
        int4 s4 = ((const int4*)esg)[i];
        int4 r4 = ((const int4*)rel)[i];
        float4 t4 = ((const float4*)tm)[i];
        int4 sr4 = ((const int4*)esrc)[i];
        int dd[4] = {d4.x, d4.y, d4.z, d4.w};
        int ss[4] = {s4.x, s4.y, s4.z, s4.w};
        int rr[4] = {r4.x, r4.y, r4.z, r4.w};
        float tt[4] = {t4.x, t4.y, t4.z, t4.w};
        int sc[4] = {sr4.x, sr4.y, sr4.z, sr4.w};
#pragma unroll
        for (int q = 0; q < 4; q++) {
            if (dd[q] == __ldg(&tli[ss[q]])) {
                bool inb = (rr[q] < NET);
                int old = atomicAdd(&g_ecnt[ss[q]], inb ? 0x10001 : 1);
                int pos = old & 0xFFFF;
                float t = tt[q];
                unsigned pk = (unsigned)(i * 4 + q) | (inb ? 0x80000000u : 0u);
                float4 mt;
                mt.x = __uint_as_float(pk);
                mt.y = __int_as_float(sc[q]);
                mt.z = expf(-t);
                mt.w = expf(-t * (1.0f / 24.0f));
                g_emeta[(size_t)ss[q] * ECAP + pos] = mt;
            }
        }
    } else {
        int i = (b - EBLK) * 256 + threadIdx.x;
        int4 n4 = ((const int4*)nsg)[i];
        int4 h4 = ((const int4*)hop)[i];
        int nn[4] = {n4.x, n4.y, n4.z, n4.w};
        int hh[4] = {h4.x, h4.y, h4.z, h4.w};
#pragma unroll
        for (int q = 0; q < 4; q++) {
            bool h1 = (hh[q] == 1);
            int old = atomicAdd(&g_ncnt[nn[q]], h1 ? 0x10001 : 1);
            int pos = old & 0xFFFF;
            g_nlist[(size_t)nn[q] * NCAP + pos] =
                (unsigned)(i * 4 + q) | (h1 ? 0x80000000u : 0u);
        }
    }
}

// ---------------- block reduce helpers (128 threads) ------------------------
__device__ __forceinline__ float blk_sum(float v, float* sb) {
#pragma unroll
    for (int o = 16; o > 0; o >>= 1) v += __shfl_xor_sync(0xffffffffu, v, o);
    __syncthreads();
    if ((threadIdx.x & 31) == 0) sb[threadIdx.x >> 5] = v;
    __syncthreads();
    return sb[0] + sb[1] + sb[2] + sb[3];
}
__device__ __forceinline__ float blk_ln(float x, float* sb) {
    float m = blk_sum(x, sb) * (1.0f / 128.0f);
    float d = x - m;
    float v = blk_sum(d * d, sb) * (1.0f / 128.0f);
    return d * rsqrtf(v + 1e-5f);
}

// ---------------- merged aggregation: grid 3T, interleaved b%3 ---------------
__global__ void __launch_bounds__(128, 10) k_agg(const float* __restrict__ edge_repr,
                                                 const float* __restrict__ node_repr,
                                                 const float* __restrict__ W1,
                                                 const float* __restrict__ b1) {
    __shared__ __align__(16) char sbuf[4096 + 8192 + 128];
    float4*   smeta4 = (float4*)sbuf;
    unsigned* smetau = (unsigned*)sbuf;
    float* cmb  = (float*)(sbuf + 4096);
    float* scmb = (float*)(sbuf + 4096 + 8192);
    float* sb   = scmb + 24;

    int b = blockIdx.x;
    int type = b % 3;
    int t = b / 3;
    int tid = threadIdx.x;
    int wid = tid >> 5, lane = tid & 31;
    int c4 = lane << 2;
    int h = tid;

    if (type == 0) {
        int epk = g_ecnt[t];
        int ecount = epk & 0xFFFF;
        const float4* ebase = g_emeta + (size_t)t * ECAP;
        for (int i = tid; i < ecount; i += 128) smeta4[i] = ebase[i];
        __syncthreads();

        float4 v_is = {0,0,0,0}, v_os = {0,0,0,0}, v_il = {0,0,0,0}, v_ol = {0,0,0,0};
        float d_is = 0, d_os = 0, d_il = 0, d_ol = 0, tsum = 0;
#pragma unroll 4
        for (int i = wid; i < ecount; i += 4) {
            float4 mt = smeta4[i];
            unsigned pk = __float_as_uint(mt.x);
            int eidx = pk & 0x7fffffff;
            float sw = mt.z, lw = mt.w;
            float4 er = *(const float4*)(edge_repr + (size_t)eidx * H + c4);
            if (pk & 0x80000000u) {
                v_is.x += sw * er.x; v_is.y += sw * er.y; v_is.z += sw * er.z; v_is.w += sw * er.w;
                v_il.x += lw * er.x; v_il.y += lw * er.y; v_il.z += lw * er.z; v_il.w += lw * er.w;
                d_is += sw; d_il += lw;
            } else {
                v_os.x += sw * er.x; v_os.y += sw * er.y; v_os.z += sw * er.z; v_os.w += sw * er.w;
                v_ol.x += lw * er.x; v_ol.y += lw * er.y; v_ol.z += lw * er.z; v_ol.w += lw * er.w;
                d_os += sw; d_ol += lw;
            }
            tsum += -__logf(sw);
        }

        *(float4*)&cmb[(wid * 4 + 0) * 128 + c4] = v_is;
        *(float4*)&cmb[(wid * 4 + 1) * 128 + c4] = v_os;
        *(float4*)&cmb[(wid * 4 + 2) * 128 + c4] = v_il;
        *(float4*)&cmb[(wid * 4 + 3) * 128 + c4] = v_ol;
        if (lane == 0) {
            scmb[wid * 5 + 0] = d_is; scmb[wid * 5 + 1] = d_os;
            scmb[wid * 5 + 2] = d_il; scmb[wid * 5 + 3] = d_ol;
            scmb[wid * 5 + 4] = tsum;
        }
        __syncthreads();

        float a_is = cmb[0 * 128 + h] + cmb[4 * 128 + h] + cmb[8 * 128 + h] + cmb[12 * 128 + h];
        float a_os = cmb[1 * 128 + h] + cmb[5 * 128 + h] + cmb[9 * 128 + h] + cmb[13 * 128 + h];
        float a_il = cmb[2 * 128 + h] + cmb[6 * 128 + h] + cmb[10 * 128 + h] + cmb[14 * 128 + h];
        float a_ol = cmb[3 * 128 + h] + cmb[7 * 128 + h] + cmb[11 * 128 + h] + cmb[15 * 128 + h];
        d_is = scmb[0] + scmb[5] + scmb[10] + scmb[15];
        d_os = scmb[1] + scmb[6] + scmb[11] + scmb[16];
        d_il = scmb[2] + scmb[7] + scmb[12] + scmb[17];
        d_ol = scmb[3] + scmb[8] + scmb[13] + scmb[18];
        tsum = scmb[4] + scmb[9] + scmb[14] + scmb[19];

        float in_s  = a_is / fmaxf(d_is, 1e-6f);
        float out_s = a_os / fmaxf(d_os, 1e-6f);
        float in_l  = a_il / fmaxf(d_il, 1e-6f);
        float out_l = a_ol / fmaxf(d_ol, 1e-6f);

        float burst = blk_ln(in_s + out_s - in_l - out_l, sb);
        float dirg  = blk_ln(out_l - in_l, sb);
        float asym  = blk_ln(fabsf(dirg), sb);
        float rb    = blk_ln(in_l + out_l, sb);

        float ssd = blk_sum(dirg * dirg, sb);
        if (h == 0) atomicAdd(&g_norm3[2], sqrtf(ssd));

        storeA(t, 0 * H + h, burst);
        storeA(t, 1 * H + h, dirg);
        storeA(t, 4 * H + h, asym);
        storeA(t, 7 * H + h, rb);

        if (h < 32) {
            float cin = (float)(epk >> 16);
            float cnt = (float)ecount;
            float cout = cnt - cin;
            int npk = g_ncnt[t];
            float c1 = (float)(npk >> 16);
            float c2 = (float)(npk & 0xFFFF) - c1;
            float smw = d_is + d_os;
            float lmw = d_il + d_ol;
            float s0 = log1pf(cin), s1 = log1pf(cout), s2 = log1pf(c1), s3 = log1pf(c2);
            float s4 = tsum / fmaxf(cnt, 1e-6f);
            float s5 = smw, s6 = lmw, s7 = smw - lmw;
            float acc = b1[h];
            acc += s0 * W1[0 * 32 + h] + s1 * W1[1 * 32 + h] + s2 * W1[2 * 32 + h] + s3 * W1[3 * 32 + h]
                 + s4 * W1[4 * 32 + h] + s5 * W1[5 * 32 + h] + s6 * W1[6 * 32 + h] + s7 * W1[7 * 32 + h];
            storeA(t, 8 * H + h, gelu_exact(acc));
        }
    } else if (type == 1) {
        int ecount = g_ecnt[t] & 0xFFFF;
        const float4* ebase = g_emeta + (size_t)t * ECAP;
        for (int i = tid; i < ecount; i += 128) smeta4[i] = ebase[i];
        __syncthreads();

        float4 v_hs = {0,0,0,0}, v_hl = {0,0,0,0};
        float smw = 0, lmw = 0;
#pragma unroll 4
        for (int i = wid; i < ecount; i += 4) {
            float4 mt = smeta4[i];
            int src = __float_as_int(mt.y);
            float sw = mt.z, lw = mt.w;
            float4 sr = *(const float4*)(node_repr + (size_t)src * H + c4);
            v_hs.x += sw * sr.x; v_hs.y += sw * sr.y; v_hs.z += sw * sr.z; v_hs.w += sw * sr.w;
            v_hl.x += lw * sr.x; v_hl.y += lw * sr.y; v_hl.z += lw * sr.z; v_hl.w += lw * sr.w;
            smw += sw; lmw += lw;
        }
        *(float4*)&cmb[(wid * 2 + 0) * 128 + c4] = v_hs;
        *(float4*)&cmb[(wid * 2 + 1) * 128 + c4] = v_hl;
        if (lane == 0) { scmb[wid * 2 + 0] = smw; scmb[wid * 2 + 1] = lmw; }
        __syncthreads();

        float a_hs = cmb[0 * 128 + h] + cmb[2 * 128 + h] + cmb[4 * 128 + h] + cmb[6 * 128 + h];
        float a_hl = cmb[1 * 128 + h] + cmb[3 * 128 + h] + cmb[5 * 128 + h] + cmb[7 * 128 + h];
        smw = scmb[0] + scmb[2] + scmb[4] + scmb[6];
        lmw = scmb[1] + scmb[3] + scmb[5] + scmb[7];

        float h1es = a_hs / fmaxf(smw, 1e-6f);
        float h1el = a_hl / fmaxf(lmw, 1e-6f);
        float slg = blk_ln(h1es - h1el, sb);
        float sss = blk_sum(slg * slg, sb);
        if (h == 0) atomicAdd(&g_norm3[1], sqrtf(sss));
        storeA(t, 3 * H + h, slg);
    } else {
        int npk = g_ncnt[t];
        int ncount = npk & 0xFFFF;
        const unsigned* nbase = g_nlist + (size_t)t * NCAP;
        for (int i = tid; i < ncount; i += 128) smetau[i] = nbase[i];
        __syncthreads();

        float4 v_h1 = {0,0,0,0}, v_h2 = {0,0,0,0};
#pragma unroll 4
        for (int i = wid; i < ncount; i += 4) {
            unsigned pk = smetau[i];
            float4 nr = *(const float4*)(node_repr + (size_t)(pk & 0x7fffffff) * H + c4);
            if (pk & 0x80000000u) {
                v_h1.x += nr.x; v_h1.y += nr.y; v_h1.z += nr.z; v_h1.w += nr.w;
            } else {
                v_h2.x += nr.x; v_h2.y += nr.y; v_h2.z += nr.z; v_h2.w += nr.w;
            }
        }
        *(float4*)&cmb[(wid * 2 + 0) * 128 + c4] = v_h1;
        *(float4*)&cmb[(wid * 2 + 1) * 128 + c4] = v_h2;
        __syncthreads();

        float a_h1 = cmb[0 * 128 + h] + cmb[2 * 128 + h] + cmb[4 * 128 + h] + cmb[6 * 128 + h];
        float a_h2 = cmb[1 * 128 + h] + cmb[3 * 128 + h] + cmb[5 * 128 + h] + cmb[7 * 128 + h];
        float c1 = (float)(npk >> 16);
        float c2 = (float)ncount - c1;

        float h1m = a_h1 / fmaxf(c1, 1e-6f);
        float h2m = a_h2 / fmaxf(c2, 1e-6f);

        float hopg = blk_ln(h1m - h2m, sb);
        float h1n  = blk_ln(h1m, sb);
        float h2n  = blk_ln(h2m, sb);

        float ssh = blk_sum(hopg * hopg, sb);
        if (h == 0) atomicAdd(&g_norm3[0], sqrtf(ssh));

        storeA(t, 2 * H + h, hopg);
        storeA(t, 5 * H + h, h1n);
        storeA(t, 6 * H + h, h2n);
    }
}

// ---------------- GEMM1: smem-staged, warp tile 32x16, 8 warps, 256 blocks --
// BM=64 BN=64, 256 threads = 8 warps (2m x 4n), grid (64,4) = 256 blocks.
// smem 32KB/block -> 2 blocks/SM = 16 warps/SM; LDS 375B/mma.
__global__ void __launch_bounds__(256) k_gemm1(const float* __restrict__ b2) {
    __shared__ __align__(16) float sA[2][2048];  // [(mt*4 + u)*128 + i]
    __shared__ __align__(16) float sB[2][2048];  // [(u*8 + nt)*64 + i]
    int tid = threadIdx.x, lane = tid & 31, warp = tid >> 5;
    int wm = warp & 1, wn = warp >> 1;           // wm 0..1, wn 0..3
    int bm = blockIdx.x * 64, bn = blockIdx.y * 64;
    int mt0 = bm >> 4;            // first of 4 m16 tiles
    int ntB = bn >> 3;            // first of 8 n8 tiles

    // A copy: 2 float4 per thread per buffer (2048 floats)
    int a_mt[2], a_u[2], a_i[2];
#pragma unroll
    for (int q = 0; q < 2; q++) {
        int flat = (tid + q * 256) * 4;
        a_mt[q] = flat >> 9;
        a_u[q]  = (flat >> 7) & 3;
        a_i[q]  = flat & 127;
    }
    // B copy: 2 float4 per thread per buffer (2048 floats)
    int b_u[2], b_nt[2], b_i[2];
#pragma unroll
    for (int q = 0; q < 2; q++) {
        int flat = (tid + q * 256) * 4;
        b_u[q]  = flat >> 9;
        b_nt[q] = (flat >> 6) & 7;
        b_i[q]  = flat & 63;
    }
    uint32_t sA_addr[2][2], sB_addr[2][2];
#pragma unroll
    for (int s = 0; s < 2; s++) {
#pragma unroll
        for (int q = 0; q < 2; q++) {
            sA_addr[s][q] = smem_u32(&sA[s][(a_mt[q] * 4 + a_u[q]) * 128 + a_i[q]]);
            sB_addr[s][q] = smem_u32(&sB[s][(b_u[q] * 8 + b_nt[q]) * 64 + b_i[q]]);
        }
    }

    float c[2][2][4];
#pragma unroll
    for (int mi = 0; mi < 2; mi++)
#pragma unroll
        for (int j = 0; j < 2; j++)
#pragma unroll
            for (int r = 0; r < 4; r++) c[mi][j][r] = 0.0f;

    const int NG = KS / 4;  // 33 groups

    // prefetch group 0
#pragma unroll
    for (int q = 0; q < 2; q++) {
        cpa16(sA_addr[0][q], g_Af + ((size_t)(mt0 + a_mt[q]) * KS + a_u[q]) * 128 + a_i[q]);
        cpa16(sB_addr[0][q], g_Bf + ((size_t)b_u[q] * 32 + ntB + b_nt[q]) * 64 + b_i[q]);
    }
    CP_COMMIT();

    for (int g = 0; g < NG; g++) {
        int cur = g & 1;
        if (g + 1 < NG) {
            int nxt = cur ^ 1;
            int ks0 = (g + 1) * 4;
#pragma unroll
            for (int q = 0; q < 2; q++) {
                cpa16(sA_addr[nxt][q],
                      g_Af + ((size_t)(mt0 + a_mt[q]) * KS + ks0 + a_u[q]) * 128 + a_i[q]);
                cpa16(sB_addr[nxt][q],
                      g_Bf + ((size_t)(ks0 + b_u[q]) * 32 + ntB + b_nt[q]) * 64 + b_i[q]);
            }
            CP_COMMIT();
            CP_WAIT(1);
        } else {
            CP_WAIT(0);
        }
        __syncthreads();

        const float* Ab = &sA[cur][(wm * 2 * 4) * 128 + lane * 4];
        const float* Bb = &sB[cur][(wn * 2) * 64 + lane * 2];
#pragma unroll
        for (int u = 0; u < 4; u++) {
            float4 a0 = *(const float4*)(Ab + u * 128);
            float4 a1 = *(const float4*)(Ab + (4 + u) * 128);
            float2 b0 = *(const float2*)(Bb + (u * 8 + 0) * 64);
            float2 b1v = *(const float2*)(Bb + (u * 8 + 1) * 64);
            mma8(c[0][0], a0, b0);
            mma8(c[1][0], a1, b0);
            mma8(c[0][1], a0, b1v);
            mma8(c[1][1], a1, b1v);
        }
        __syncthreads();
    }

#pragma unroll
    for (int mi = 0; mi < 2; mi++) {
        int r0 = bm + wm * 32 + mi * 16 + (lane >> 2);
#pragma unroll
        for (int j = 0; j < 2; j++) {
            int cc = bn + wn * 16 + j * 8 + (lane & 3) * 2;
            float bx = b2[cc], by = b2[cc + 1];
            float2 lo, hi;
            lo.x = gelu_exact(c[mi][j][0] + bx);
            lo.y = gelu_exact(c[mi][j][1] + by);
            hi.x = gelu_exact(c[mi][j][2] + bx);
            hi.y = gelu_exact(c[mi][j][3] + by);
            *(float2*)(g_hidden + (size_t)r0 * HD + cc) = lo;
            *(float2*)(g_hidden + (size_t)(r0 + 8) * HD + cc) = hi;
        }
    }
}

// ---------------- GEMM2: [T,256] @ [256,128] + bias + 0.25*tanh + norms -----
__global__ void __launch_bounds__(256) k_gemm2(const float* __restrict__ W3,
                                               const float* __restrict__ b3,
                                               float* __restrict__ out) {
    __shared__ float hs[16 * 256];
    int tid = threadIdx.x;
    int t0 = blockIdx.x * 16;
    if (blockIdx.x == 0 && tid < 3)
        out[(size_t)T * H + tid] = g_norm3[tid] * (1.0f / (float)T);
    for (int i = tid; i < 16 * 256; i += 256)
        hs[i] = g_hidden[(size_t)t0 * 256 + i];
    __syncthreads();
    int n = tid & 127;
    int half = tid >> 7;
    const float* hp = hs + half * 8 * 256;
    u64 acc2[8];
#pragma unroll
    for (int r = 0; r < 8; r++) acc2[r] = 0ull;
    for (int k = 0; k < 256; k += 4) {
        float w0 = W3[(k + 0) * 128 + n];
        float w1 = W3[(k + 1) * 128 + n];
        float w2 = W3[(k + 2) * 128 + n];
        float w3v = W3[(k + 3) * 128 + n];
        u64 w01 = pack2(w0, w1);
        u64 w23 = pack2(w2, w3v);
#pragma unroll
        for (int r = 0; r < 8; r++) {
            ulonglong2 hv = *(const ulonglong2*)&hp[r * 256 + k];
            fma2(acc2[r], hv.x, w01);
            fma2(acc2[r], hv.y, w23);
        }
    }
    float bias = b3[n];
#pragma unroll
    for (int r = 0; r < 8; r++) {
        float lo, hi;
        unpack2(acc2[r], lo, hi);
        out[(size_t)(t0 + half * 8 + r) * 128 + n] = 0.25f * tanhf(lo + hi + bias);
    }
}

// ---------------- launcher --------------------------------------------------
extern "C" void kernel_launch(void* const* d_in, const int* in_sizes, int n_in,
                              void* d_out, int out_size) {
    const float* node_repr = (const float*)d_in[0];
    const float* edge_repr = (const float*)d_in[1];
    const int*   edge_src  = (const int*)d_in[2];
    const int*   edge_dst  = (const int*)d_in[3];
    const int*   rel_ids   = (const int*)d_in[4];
    const float* etime     = (const float*)d_in[5];
    const int*   tli       = (const int*)d_in[6];
    const int*   nsg       = (const int*)d_in[7];
    const int*   esg       = (const int*)d_in[8];
    const int*   hop       = (const int*)d_in[9];
    const float* W1 = (const float*)d_in[10];
    const float* b1 = (const float*)d_in[11];
    const float* W2 = (const float*)d_in[12];
    const float* b2 = (const float*)d_in[13];
    const float* W3 = (const float*)d_in[14];
    const float* b3 = (const float*)d_in[15];
    float* out = (float*)d_out;

    k_initcvt<<<FD * HD / 256, 256>>>(W2);
    k_scatter<<<EBLK + NBLK, 256>>>(edge_dst, esg, tli, rel_ids, etime, edge_src, nsg, hop);
    k_agg<<<3 * T, 128>>>(edge_repr, node_repr, W1, b1);
    k_gemm1<<<dim3(64, 4), 256>>>(b2);
    k_gemm2<<<T / 16, 256>>>(W3, b3, out);
}